// round 12
// baseline (speedup 1.0000x reference)
#include <cuda_runtime.h>
#include <cuda_bf16.h>
#include <cstdint>
#include <math.h>

#define B_      1024
#define H_      256
#define G3_     768
#define LPRE    60
#define LFWD    80
#define ML_     80

// ---------------- static device scratch (no allocation) ----------------
__device__ float g_catpre64[LPRE * B_ * 64];
__device__ float g_Mf64[G3_ * 64];
__device__ float g_gibias[G3_];
__device__ float g_GIenc[LPRE * B_ * G3_];
__device__ float g_ENC[LPRE * B_ * H_];
__device__ float g_M1[H_ * H_];
__device__ float g_c1[H_];
__device__ float g_c0fix[H_];
__device__ float g_Xe[LFWD * B_ * H_];
__device__ float g_Wstack[2 * G3_ * H_];
__device__ float g_bstack[2 * G3_];
__device__ float g_lp[B_ * 384];           // [logits(128) | pre(256)] per row
__device__ float g_g[B_ * H_];
__device__ float g_gigh[B_ * 2 * G3_];
__device__ float g_gh[B_ * G3_];
__device__ float g_hbuf[2][B_ * H_];
__device__ float g_Hall[LFWD * B_ * H_];
__device__ float g_Wh_pad[128 * H_];
__device__ float g_W2[384 * H_];           // rows 0-127: Wfuse, rows 128-383: Wch
__device__ float g_WexC[384 * H_];         // rows 0-127: We_pad, rows 128-383: combW_e
__device__ float g_bias384[384];           // [attn_b | comb_b]
__device__ float g_corr_l[128];
__device__ float g_corr_c[H_];             // combW_e . c0fix
__device__ float g_XLC[LFWD * B_ * 384];   // Xe@WexC^T + bias384

// ================= helpers =================
__device__ __forceinline__ uint32_t smem_u32(const void* p) {
    uint32_t a;
    asm("{ .reg .u64 t; cvta.to.shared.u64 t, %1; cvt.u32.u64 %0, t; }" : "=r"(a) : "l"(p));
    return a;
}

#define STS128(r0, r1, r2, r3, smem_addr) \
    asm volatile("st.shared.v4.b32 [%0], {%1, %2, %3, %4};" \
        :: "r"(smem_addr), "r"(r0), "r"(r1), "r"(r2), "r"(r3) : "memory")

#define STS64(smem_addr, r0, r1) \
    asm volatile("st.shared.v2.b32 [%0], {%1, %2};" \
        :: "r"(smem_addr), "r"(r0), "r"(r1) : "memory")

#define LDSM4(r0, r1, r2, r3, addr) \
    asm volatile("ldmatrix.sync.aligned.m8n8.x4.shared.b16 {%0,%1,%2,%3}, [%4];" \
        : "=r"(r0), "=r"(r1), "=r"(r2), "=r"(r3) : "r"(addr))

#define MMA16816(d, a, b) \
    asm volatile("mma.sync.aligned.m16n8k16.row.col.f32.bf16.bf16.f32 " \
        "{%0,%1,%2,%3},{%4,%5,%6,%7},{%8,%9},{%0,%1,%2,%3};" \
        : "+f"((d)[0]), "+f"((d)[1]), "+f"((d)[2]), "+f"((d)[3]) \
        : "r"((a)[0]), "r"((a)[1]), "r"((a)[2]), "r"((a)[3]), "r"((b)[0]), "r"((b)[1]))

__device__ __forceinline__ void cvt_hl(float x, float y, uint32_t& h, uint32_t& l) {
    __nv_bfloat162 hb = __floats2bfloat162_rn(x, y);
    float rx = x - __low2float(hb);
    float ry = y - __high2float(hb);
    __nv_bfloat162 lb = __floats2bfloat162_rn(rx, ry);
    h = *reinterpret_cast<uint32_t*>(&hb);
    l = *reinterpret_cast<uint32_t*>(&lb);
}

__device__ __forceinline__ uint32_t swz(int r, int c) {
    return (uint32_t)(r * 64 + ((c ^ ((r >> 1) & 3)) << 4));
}

__device__ __forceinline__ void ldg16(const float* __restrict__ p, float* f) {
#pragma unroll
    for (int i = 0; i < 4; i++) {
        float4 v = *(const float4*)(p + 4 * i);
        f[4 * i + 0] = v.x; f[4 * i + 1] = v.y; f[4 * i + 2] = v.z; f[4 * i + 3] = v.w;
    }
}

__device__ __forceinline__ float sigm(float x) { return 1.f / (1.f + expf(-x)); }

__device__ __forceinline__ float gru1(float ir, float iz, float inn,
                                      float hr, float hz, float hn, float hp) {
    float r = sigm(ir + hr);
    float z = sigm(iz + hz);
    float n = tanhf(inn + r * hn);
    return (1.f - z) * n + z * hp;
}

__device__ __forceinline__ void sts_half(uint32_t sh, uint32_t sl, int row, int c0, const float* f) {
    uint32_t h[8], l[8];
#pragma unroll
    for (int i = 0; i < 8; i++) cvt_hl(f[2 * i], f[2 * i + 1], h[i], l[i]);
    uint32_t o0 = swz(row, c0), o1 = swz(row, c0 + 1);
    STS128(h[0], h[1], h[2], h[3], sh + o0);
    STS128(h[4], h[5], h[6], h[7], sh + o1);
    STS128(l[0], l[1], l[2], l[3], sl + o0);
    STS128(l[4], l[5], l[6], l[7], sl + o1);
}

// ================= BM=128 mma.sync bf16x3 GEMM (prework) =============
#define MG_SMEM (2 * 32768)
#define OFF_AH 0u
#define OFF_AL 8192u
#define OFF_BH 16384u
#define OFF_BL 24576u

__global__ __launch_bounds__(256, 1) void mmagemm_kernel(
    const float* __restrict__ A0, int lda0,
    const float* __restrict__ W, int ldw,
    const float* __restrict__ bias,
    float* __restrict__ C, int ldc,
    int M, int N, int K)
{
    extern __shared__ char dsm[];
    uint32_t sb = smem_u32(dsm);
    int tid = threadIdx.x, lane = tid & 31, wid = tid >> 5;
    int bm = blockIdx.y * 128, bn = blockIdx.x * 128;
    int warpM = wid & 3, warpN = wid >> 2;

    int lrow = tid >> 1, lhalf = tid & 1;
    const float* rowA = A0 + (size_t)(bm + lrow) * lda0 + lhalf * 16;
    const float* bp = W + (size_t)(bn + lrow) * ldw + lhalf * 16;

    float acc[2][8][4];
#pragma unroll
    for (int i = 0; i < 2; i++)
#pragma unroll
        for (int j = 0; j < 8; j++)
#pragma unroll
            for (int q = 0; q < 4; q++) acc[i][j][q] = 0.f;

    float fa[16], fb[16];
    int nk = K >> 5;

    ldg16(rowA, fa);
    ldg16(bp, fb);
    sts_half(sb + OFF_AH, sb + OFF_AL, lrow, lhalf * 2, fa);
    sts_half(sb + OFF_BH, sb + OFF_BL, lrow, lhalf * 2, fb);
    __syncthreads();

    for (int i = 0; i < nk; i++) {
        if (i + 1 < nk) {
            ldg16(rowA + (i + 1) * 32, fa);
            ldg16(bp + (i + 1) * 32, fb);
        }
        uint32_t st = sb + (uint32_t)(i & 1) * 32768u;
#pragma unroll
        for (int ks = 0; ks < 2; ks++) {
            uint32_t ah[2][4], al[2][4], bh[8][2], bl[8][2];
#pragma unroll
            for (int mf = 0; mf < 2; mf++) {
                int r = warpM * 32 + mf * 16 + (lane & 15);
                int c = ks * 2 + (lane >> 4);
                uint32_t o = swz(r, c);
                LDSM4(ah[mf][0], ah[mf][1], ah[mf][2], ah[mf][3], st + OFF_AH + o);
                LDSM4(al[mf][0], al[mf][1], al[mf][2], al[mf][3], st + OFF_AL + o);
            }
#pragma unroll
            for (int p = 0; p < 4; p++) {
                int r = warpN * 64 + p * 16 + (lane & 7) + ((lane >> 4) << 3);
                int c = ks * 2 + ((lane >> 3) & 1);
                uint32_t o = swz(r, c);
                LDSM4(bh[2 * p][0], bh[2 * p][1], bh[2 * p + 1][0], bh[2 * p + 1][1], st + OFF_BH + o);
                LDSM4(bl[2 * p][0], bl[2 * p][1], bl[2 * p + 1][0], bl[2 * p + 1][1], st + OFF_BL + o);
            }
#pragma unroll
            for (int mf = 0; mf < 2; mf++)
#pragma unroll
                for (int nf = 0; nf < 8; nf++) {
                    MMA16816(acc[mf][nf], ah[mf], bh[nf]);
                    MMA16816(acc[mf][nf], ah[mf], bl[nf]);
                    MMA16816(acc[mf][nf], al[mf], bh[nf]);
                }
        }
        if (i + 1 < nk) {
            uint32_t st2 = sb + (uint32_t)((i + 1) & 1) * 32768u;
            sts_half(st2 + OFF_AH, st2 + OFF_AL, lrow, lhalf * 2, fa);
            sts_half(st2 + OFF_BH, st2 + OFF_BL, lrow, lhalf * 2, fb);
            __syncthreads();
        }
    }

#pragma unroll
    for (int mf = 0; mf < 2; mf++)
#pragma unroll
        for (int nf = 0; nf < 8; nf++) {
            int m0 = bm + warpM * 32 + mf * 16 + (lane >> 2);
            int n = bn + warpN * 64 + nf * 8 + (lane & 3) * 2;
            float b0 = 0.f, b1 = 0.f;
            if (bias) { b0 = bias[n]; b1 = bias[n + 1]; }
#pragma unroll
            for (int hh = 0; hh < 2; hh++) {
                int m = m0 + hh * 8;
                float2 vv = make_float2(acc[mf][nf][2 * hh] + b0, acc[mf][nf][2 * hh + 1] + b1);
                *(float2*)(C + (size_t)m * ldc + n) = vv;
            }
        }
}

// ================= BM=64 mma GEMM (serial path) =================
#define MG64_SMEM (2 * 24576)
#define O64_AH 0u
#define O64_AL 4096u
#define O64_BH 8192u
#define O64_BL 16384u

__global__ __launch_bounds__(256, 1) void mmagemm64_kernel(
    const float* __restrict__ A0, const float* __restrict__ A1, int splitN, int lda0,
    const float* __restrict__ W, int ldw,
    const float* __restrict__ bias,
    const float* __restrict__ addmat, int ldadd,
    float* __restrict__ C, int ldc,
    int M, int N, int K, int act)
{
    extern __shared__ char dsm[];
    uint32_t sb = smem_u32(dsm);
    int tid = threadIdx.x, lane = tid & 31, wid = tid >> 5;
    int bm = blockIdx.y * 64, bn = blockIdx.x * 128;
    const float* __restrict__ A = (bn < splitN) ? A0 : A1;
    int warpM = wid & 1, warpN = wid >> 1;

    int lrow = tid >> 1, lhalf = tid & 1;
    int arow = (tid & 127) >> 1;
    bool doA = tid < 128;
    const float* rowA = A + (size_t)(bm + arow) * lda0 + lhalf * 16;
    const float* bp = W + (size_t)(bn + lrow) * ldw + lhalf * 16;

    float acc[2][4][4];
#pragma unroll
    for (int i = 0; i < 2; i++)
#pragma unroll
        for (int j = 0; j < 4; j++)
#pragma unroll
            for (int q = 0; q < 4; q++) acc[i][j][q] = 0.f;

    float fa[16], fb[16];
    int nk = K >> 5;

    {
        ldg16(bp, fb);
        if (doA) ldg16(rowA, fa);
        sts_half(sb + O64_BH, sb + O64_BL, lrow, lhalf * 2, fb);
        if (doA) sts_half(sb + O64_AH, sb + O64_AL, arow, lhalf * 2, fa);
    }
    __syncthreads();

    for (int i = 0; i < nk; i++) {
        if (i + 1 < nk) {
            int kk = (i + 1) * 32;
            ldg16(bp + kk, fb);
            if (doA) ldg16(rowA + kk, fa);
        }
        uint32_t st = sb + (uint32_t)(i & 1) * 24576u;
#pragma unroll
        for (int ks = 0; ks < 2; ks++) {
            uint32_t ah[2][4], al[2][4], bh[4][2], bl[4][2];
#pragma unroll
            for (int mf = 0; mf < 2; mf++) {
                int r = warpM * 32 + mf * 16 + (lane & 15);
                int c = ks * 2 + (lane >> 4);
                uint32_t o = swz(r, c);
                LDSM4(ah[mf][0], ah[mf][1], ah[mf][2], ah[mf][3], st + O64_AH + o);
                LDSM4(al[mf][0], al[mf][1], al[mf][2], al[mf][3], st + O64_AL + o);
            }
#pragma unroll
            for (int p = 0; p < 2; p++) {
                int r = warpN * 32 + p * 16 + (lane & 7) + ((lane >> 4) << 3);
                int c = ks * 2 + ((lane >> 3) & 1);
                uint32_t o = swz(r, c);
                LDSM4(bh[2 * p][0], bh[2 * p][1], bh[2 * p + 1][0], bh[2 * p + 1][1], st + O64_BH + o);
                LDSM4(bl[2 * p][0], bl[2 * p][1], bl[2 * p + 1][0], bl[2 * p + 1][1], st + O64_BL + o);
            }
#pragma unroll
            for (int mf = 0; mf < 2; mf++)
#pragma unroll
                for (int nf = 0; nf < 4; nf++) {
                    MMA16816(acc[mf][nf], ah[mf], bh[nf]);
                    MMA16816(acc[mf][nf], ah[mf], bl[nf]);
                    MMA16816(acc[mf][nf], al[mf], bh[nf]);
                }
        }
        if (i + 1 < nk) {
            uint32_t st2 = sb + (uint32_t)((i + 1) & 1) * 24576u;
            sts_half(st2 + O64_BH, st2 + O64_BL, lrow, lhalf * 2, fb);
            if (doA) sts_half(st2 + O64_AH, st2 + O64_AL, arow, lhalf * 2, fa);
            __syncthreads();
        }
    }

#pragma unroll
    for (int mf = 0; mf < 2; mf++)
#pragma unroll
        for (int nf = 0; nf < 4; nf++) {
            int m0 = bm + warpM * 32 + mf * 16 + (lane >> 2);
            int n = bn + warpN * 32 + nf * 8 + (lane & 3) * 2;
            float b0 = 0.f, b1 = 0.f;
            if (bias) { b0 = bias[n]; b1 = bias[n + 1]; }
#pragma unroll
            for (int hh = 0; hh < 2; hh++) {
                int m = m0 + hh * 8;
                float v0 = acc[mf][nf][2 * hh] + b0;
                float v1 = acc[mf][nf][2 * hh + 1] + b1;
                if (addmat) {
                    const float* am = addmat + (size_t)m * ldadd + n;
                    v0 += am[0]; v1 += am[1];
                }
                if (act == 1) { v0 = tanhf(v0); v1 = tanhf(v1); }
                float2 vv = make_float2(v0, v1);
                *(float2*)(C + (size_t)m * ldc + n) = vv;
            }
        }
}

// ================= fused softmax + ctx + comb kernel =================
// 64 blocks x 16 batch rows. dsm: A_hi 8KB | A_lo 8KB | B stages 2x32KB = 80KB
#define FC_SMEM 81920
#define FCA_H 0u
#define FCA_L 8192u
#define FCB   16384u

__global__ __launch_bounds__(256, 1) void smctxcomb_kernel(
    const float* __restrict__ lp,       // [B,384], logits in cols 0-79
    const float* __restrict__ ENC,      // [60,B,256]
    const float* __restrict__ Wc,       // combW+256, ld 512
    const float* __restrict__ addmat,   // pre base (lp+128 or XLC+128), ld 384
    const float* __restrict__ bias,     // corr_c (t=0) or null
    float* __restrict__ gout)           // [B,256]
{
    extern __shared__ char dsm[];
    __shared__ float saw[16][ML_];
    uint32_t sb = smem_u32(dsm);
    int tid = threadIdx.x, lane = tid & 31, wid = tid >> 5;
    int b0 = blockIdx.x * 16;

    // ---- softmax: warp w -> rows 2w, 2w+1 ----
#pragma unroll
    for (int q = 0; q < 2; q++) {
        int rr = wid * 2 + q;
        const float* lb = lp + (size_t)(b0 + rr) * 384;
        float x0 = lb[lane], x1 = lb[lane + 32];
        float x2 = (lane < 16) ? lb[lane + 64] : -1e30f;
        float mx = fmaxf(x0, fmaxf(x1, x2));
#pragma unroll
        for (int o = 16; o; o >>= 1) mx = fmaxf(mx, __shfl_xor_sync(0xffffffffu, mx, o));
        float e0 = expf(x0 - mx), e1 = expf(x1 - mx);
        float e2 = (lane < 16) ? expf(x2 - mx) : 0.f;
        float s = e0 + e1 + e2;
#pragma unroll
        for (int o = 16; o; o >>= 1) s += __shfl_xor_sync(0xffffffffu, s, o);
        float inv = 1.f / s;
        saw[rr][lane] = e0 * inv;
        saw[rr][lane + 32] = e1 * inv;
        if (lane < 16) saw[rr][lane + 64] = e2 * inv;
    }
    __syncthreads();

    // ---- ctx: thread (rg = tid>>6, cc = tid&63): rows rg*4+0..3, cols 4cc..4cc+3 ----
    int rg = tid >> 6, cc = tid & 63;
    float a4[4][4];
#pragma unroll
    for (int r = 0; r < 4; r++)
#pragma unroll
        for (int j = 0; j < 4; j++) a4[r][j] = 0.f;

    const float* ep = ENC + (size_t)b0 * 256 + cc * 4;
    for (int m = 0; m < LPRE; m += 2) {
        const float* em0 = ep + (size_t)m * B_ * 256;
        const float* em1 = ep + (size_t)(m + 1) * B_ * 256;
#pragma unroll
        for (int r = 0; r < 4; r++) {
            int rr = rg * 4 + r;
            float4 e0 = *(const float4*)(em0 + (size_t)rr * 256);
            float4 e1 = *(const float4*)(em1 + (size_t)rr * 256);
            float w0 = saw[rr][m], w1 = saw[rr][m + 1];
            a4[r][0] += w0 * e0.x + w1 * e1.x;
            a4[r][1] += w0 * e0.y + w1 * e1.y;
            a4[r][2] += w0 * e0.z + w1 * e1.z;
            a4[r][3] += w0 * e0.w + w1 * e1.w;
        }
    }
    // write ctx to A smem (bf16 hi/lo), k-chunk layout: chunk ki has 16 rows x 32 cols
    {
        int ki = cc >> 3;              // 8 cols of float4 per 32-col chunk
        int cl = (cc >> 1) & 3;        // 16B chunk within row
        int half = (cc & 1) * 8;       // 8B half of the 16B chunk
        uint32_t baseH = sb + FCA_H + (uint32_t)ki * 1024u;
        uint32_t baseL = sb + FCA_L + (uint32_t)ki * 1024u;
#pragma unroll
        for (int r = 0; r < 4; r++) {
            int rr = rg * 4 + r;
            uint32_t h0, l0, h1, l1;
            cvt_hl(a4[r][0], a4[r][1], h0, l0);
            cvt_hl(a4[r][2], a4[r][3], h1, l1);
            uint32_t o = swz(rr, cl) + half;
            STS64(baseH + o, h0, h1);
            STS64(baseL + o, l0, l1);
        }
    }

    // ---- comb MMA: g[16 x 256] = ctx @ Wc^T, K=256 in 8 chunks of 32 ----
    float fb[32];
    const float* bp = Wc + (size_t)tid * 512;   // row tid of Wc (output col n = tid)
    ldg16(bp, fb);
    ldg16(bp + 16, fb + 16);
    {
        uint32_t s0 = sb + FCB;
        sts_half(s0, s0 + 16384u, tid, 0, fb);
        sts_half(s0, s0 + 16384u, tid, 2, fb + 16);
    }
    __syncthreads();

    float acc[4][4];
#pragma unroll
    for (int j = 0; j < 4; j++)
#pragma unroll
        for (int q = 0; q < 4; q++) acc[j][q] = 0.f;

    int warpN = wid;
    for (int kic = 0; kic < 8; kic++) {
        if (kic + 1 < 8) {
            ldg16(bp + (kic + 1) * 32, fb);
            ldg16(bp + (kic + 1) * 32 + 16, fb + 16);
        }
        uint32_t stg = sb + FCB + (uint32_t)(kic & 1) * 32768u;
        uint32_t abase = (uint32_t)kic * 1024u;
#pragma unroll
        for (int ks = 0; ks < 2; ks++) {
            uint32_t ah[4], al[4];
            {
                int r = lane & 15;
                int c = ks * 2 + (lane >> 4);
                uint32_t o = swz(r, c);
                LDSM4(ah[0], ah[1], ah[2], ah[3], sb + FCA_H + abase + o);
                LDSM4(al[0], al[1], al[2], al[3], sb + FCA_L + abase + o);
            }
            uint32_t bh[4][2], bl[4][2];
#pragma unroll
            for (int p = 0; p < 2; p++) {
                int r = warpN * 32 + p * 16 + (lane & 7) + ((lane >> 4) << 3);
                int c = ks * 2 + ((lane >> 3) & 1);
                uint32_t o = swz(r, c);
                LDSM4(bh[2 * p][0], bh[2 * p][1], bh[2 * p + 1][0], bh[2 * p + 1][1], stg + o);
                LDSM4(bl[2 * p][0], bl[2 * p][1], bl[2 * p + 1][0], bl[2 * p + 1][1], stg + 16384u + o);
            }
#pragma unroll
            for (int nf = 0; nf < 4; nf++) {
                MMA16816(acc[nf], ah, bh[nf]);
                MMA16816(acc[nf], ah, bl[nf]);
                MMA16816(acc[nf], al, bh[nf]);
            }
        }
        if (kic + 1 < 8) {
            uint32_t st2 = sb + FCB + (uint32_t)((kic + 1) & 1) * 32768u;
            sts_half(st2, st2 + 16384u, tid, 0, fb);
            sts_half(st2, st2 + 16384u, tid, 2, fb + 16);
            __syncthreads();
        }
    }

    // ---- epilogue: + pre (addmat), tanh, write g ----
#pragma unroll
    for (int nf = 0; nf < 4; nf++) {
        int n = warpN * 32 + nf * 8 + (lane & 3) * 2;
        int m0 = lane >> 2;
        float bv0 = 0.f, bv1 = 0.f;
        if (bias) { bv0 = bias[n]; bv1 = bias[n + 1]; }
#pragma unroll
        for (int hh = 0; hh < 2; hh++) {
            int m = m0 + hh * 8;
            const float* am = addmat + (size_t)(b0 + m) * 384 + n;
            float v0 = tanhf(acc[nf][2 * hh] + bv0 + am[0]);
            float v1 = tanhf(acc[nf][2 * hh + 1] + bv1 + am[1]);
            *(float2*)(gout + (size_t)(b0 + m) * 256 + n) = make_float2(v0, v1);
        }
    }
}

// ---------------- SIMT fp32 GEMM (final output) ----------------
__global__ __launch_bounds__(256) void gemm_kernel(
    const float* __restrict__ A, const float* __restrict__ W, int ldw,
    const float* __restrict__ bias,
    float* __restrict__ C, int ldc,
    int M, int N, int K)
{
    __shared__ float As[16][64];
    __shared__ float Bs[16][64];
    int bn = blockIdx.x * 64;
    int bm = blockIdx.y * 64;

    int tid = threadIdx.x;
    int tx = tid & 15, ty = tid >> 4;
    int lr = tid >> 2;
    int lk = (tid & 3) * 4;

    float acc[4][4];
#pragma unroll
    for (int i = 0; i < 4; i++)
#pragma unroll
        for (int j = 0; j < 4; j++) acc[i][j] = 0.f;

    for (int k0 = 0; k0 < K; k0 += 16) {
        float4 a4 = *(const float4*)(A + (size_t)(bm + lr) * K + k0 + lk);
        As[lk + 0][lr] = a4.x; As[lk + 1][lr] = a4.y;
        As[lk + 2][lr] = a4.z; As[lk + 3][lr] = a4.w;
        float4 b4 = make_float4(0.f, 0.f, 0.f, 0.f);
        if (bn + lr < N)
            b4 = *(const float4*)(W + (size_t)(bn + lr) * ldw + k0 + lk);
        Bs[lk + 0][lr] = b4.x; Bs[lk + 1][lr] = b4.y;
        Bs[lk + 2][lr] = b4.z; Bs[lk + 3][lr] = b4.w;
        __syncthreads();
#pragma unroll
        for (int kk = 0; kk < 16; kk++) {
            float ra[4], rb[4];
#pragma unroll
            for (int i = 0; i < 4; i++) ra[i] = As[kk][ty * 4 + i];
#pragma unroll
            for (int j = 0; j < 4; j++) rb[j] = Bs[kk][tx * 4 + j];
#pragma unroll
            for (int i = 0; i < 4; i++)
#pragma unroll
                for (int j = 0; j < 4; j++) acc[i][j] += ra[i] * rb[j];
        }
        __syncthreads();
    }

#pragma unroll
    for (int i = 0; i < 4; i++) {
        int m = bm + ty * 4 + i;
#pragma unroll
        for (int j = 0; j < 4; j++) {
            int n = bn + tx * 4 + j;
            if (n < N)
                C[(size_t)m * ldc + n] = acc[i][j] + bias[n];
        }
    }
}

// ---------------- prep kernels ----------------
__global__ void pack_catpre_kernel(const float* __restrict__ px, const float* __restrict__ py,
                                   float* __restrict__ out)
{
    int idx = blockIdx.x * 256 + threadIdx.x;
    if (idx >= LPRE * B_ * 64) return;
    int c = idx & 63;
    int tb = idx >> 6;
    float v = 0.f;
    if (c < 32) v = px[(size_t)tb * 32 + c];
    else if (c < 48) v = py[(size_t)tb * 16 + (c - 32)];
    out[idx] = v;
}

__global__ void make_Mf_kernel(const float* __restrict__ Wih, const float* __restrict__ embW,
                               const float* __restrict__ embb, const float* __restrict__ bih,
                               float* __restrict__ Mf, float* __restrict__ gib)
{
    int idx = blockIdx.x * 256 + threadIdx.x;
    if (idx < G3_ * 64) {
        int i = idx >> 6, k = idx & 63;
        float s = 0.f;
        if (k < 48)
            for (int j = 0; j < H_; j++) s += Wih[(size_t)i * H_ + j] * embW[(size_t)j * 48 + k];
        Mf[idx] = s;
    } else if (idx < G3_ * 64 + G3_) {
        int i = idx - G3_ * 64;
        float s = bih[i];
        for (int j = 0; j < H_; j++) s += Wih[(size_t)i * H_ + j] * embb[j];
        gib[i] = s;
    }
}

__global__ void make_M1_kernel(const float* __restrict__ decEmbW, const float* __restrict__ decEmbb,
                               const float* __restrict__ outW, const float* __restrict__ outb,
                               float* __restrict__ M1, float* __restrict__ c1, float* __restrict__ c0fix)
{
    int idx = blockIdx.x * 256 + threadIdx.x;
    if (idx < H_ * H_) {
        int i = idx / H_, j = idx % H_;
        float s = 0.f;
        for (int k = 0; k < 16; k++) s += decEmbW[(size_t)i * 48 + k] * outW[(size_t)k * H_ + j];
        M1[idx] = s;
    } else if (idx < H_ * H_ + H_) {
        int i = idx - H_ * H_;
        float s = 0.f;
        for (int k = 0; k < 16; k++) s += decEmbW[(size_t)i * 48 + k] * outb[k];
        c1[i] = s + decEmbb[i];
        c0fix[i] = -s;
    }
}

__global__ void stack_copy_kernel(const float* __restrict__ Wih, const float* __restrict__ Whh,
                                  const float* __restrict__ bih, const float* __restrict__ bhh,
                                  float* __restrict__ Wst, float* __restrict__ bst)
{
    int idx = blockIdx.x * 256 + threadIdx.x;
    if (idx < G3_ * H_) {
        Wst[idx] = Wih[idx];
        Wst[G3_ * H_ + idx] = Whh[idx];
    }
    if (idx < G3_) { bst[idx] = bih[idx]; bst[G3_ + idx] = bhh[idx]; }
}

__global__ void zero_h_kernel(float* __restrict__ h)
{
    int idx = blockIdx.x * 256 + threadIdx.x;
    if (idx < B_ * H_) h[idx] = 0.f;
}

__global__ void make_attnprep_kernel(const float* __restrict__ attnW, const float* __restrict__ attnb,
                                     const float* __restrict__ M1, const float* __restrict__ c0fix,
                                     float* __restrict__ WexC, float* __restrict__ Wh_pad,
                                     float* __restrict__ W2, float* __restrict__ bias384,
                                     float* __restrict__ corr_l)
{
    int idx = blockIdx.x * 256 + threadIdx.x;
    if (idx >= 128 * H_) return;
    int m = idx >> 8, k = idx & 255;
    float we = 0.f, wh = 0.f, wf = 0.f;
    if (m < ML_) {
        we = attnW[(size_t)m * 512 + k];
        wh = attnW[(size_t)m * 512 + 256 + k];
        float s = wh;
        for (int j = 0; j < H_; j++) s += attnW[(size_t)m * 512 + j] * M1[(size_t)j * H_ + k];
        wf = s;
    }
    WexC[idx] = we; Wh_pad[idx] = wh; W2[idx] = wf;
    if (k == 0) {
        float ab = 0.f, cl = 0.f;
        if (m < ML_) {
            ab = attnb[m];
            for (int j = 0; j < H_; j++) cl += c0fix[j] * attnW[(size_t)m * 512 + j];
        }
        bias384[m] = ab;
        corr_l[m] = cl;
    }
}

__global__ void make_combprep_kernel(const float* __restrict__ combW, const float* __restrict__ combb,
                                     const float* __restrict__ M1, const float* __restrict__ c0fix,
                                     float* __restrict__ WexC, float* __restrict__ W2,
                                     float* __restrict__ bias384, float* __restrict__ corr_c)
{
    int idx = blockIdx.x * 256 + threadIdx.x;
    if (idx >= H_ * H_) return;
    int n = idx >> 8, k = idx & 255;
    float s = 0.f;
    for (int j = 0; j < H_; j++) s += combW[(size_t)n * 512 + j] * M1[(size_t)j * H_ + k];
    W2[(size_t)(128 + n) * H_ + k] = s;
    WexC[(size_t)(128 + n) * H_ + k] = combW[(size_t)n * 512 + k];
    if (k == 0) {
        bias384[128 + n] = combb[n];
        float cc = 0.f;
        for (int j = 0; j < H_; j++) cc += combW[(size_t)n * 512 + j] * c0fix[j];
        corr_c[n] = cc;
    }
}

// ---------------- GRU gates ----------------
__global__ __launch_bounds__(256) void gates_kernel(
    const float* __restrict__ gi, int ldgi,
    const float* __restrict__ gh, int ldgh,
    const float* __restrict__ h,
    float* __restrict__ h2, float* __restrict__ out2)
{
    int idx = blockIdx.x * 256 + threadIdx.x;
    int b = idx >> 8, j = idx & 255;
    const float* gib = gi + (size_t)b * ldgi;
    const float* ghb = gh + (size_t)b * ldgh;
    float v = gru1(gib[j], gib[256 + j], gib[512 + j],
                   ghb[j], ghb[256 + j], ghb[512 + j], h[idx]);
    h2[idx] = v;
    if (out2) out2[idx] = v;
}

// ---------------- host launcher ----------------
static inline void run_mma(const float* A, int lda, const float* W, int ldw,
                           const float* bias, float* C, int ldc, int M, int N, int K)
{
    dim3 grid(N / 128, M / 128);
    mmagemm_kernel<<<grid, 256, MG_SMEM>>>(A, lda, W, ldw, bias, C, ldc, M, N, K);
}

static inline void run_mma64(const float* A0, const float* A1, int splitN, int lda0,
                             const float* W, int ldw, const float* bias,
                             const float* addmat, int ldadd,
                             float* C, int ldc, int M, int N, int K, int act)
{
    dim3 grid(N / 128, M / 64);
    mmagemm64_kernel<<<grid, 256, MG64_SMEM>>>(A0, A1, splitN, lda0, W, ldw, bias,
                                               addmat, ldadd, C, ldc, M, N, K, act);
}

extern "C" void kernel_launch(void* const* d_in, const int* in_sizes, int n_in,
                              void* d_out, int out_size)
{
    const float* pre_x    = (const float*)d_in[0];
    const float* pre_y    = (const float*)d_in[1];
    const float* fwd_x    = (const float*)d_in[2];
    const float* encEmbW  = (const float*)d_in[3];
    const float* encEmbB  = (const float*)d_in[4];
    const float* encWih   = (const float*)d_in[5];
    const float* encWhh   = (const float*)d_in[6];
    const float* encBih   = (const float*)d_in[7];
    const float* encBhh   = (const float*)d_in[8];
    const float* decEmbW  = (const float*)d_in[9];
    const float* decEmbB  = (const float*)d_in[10];
    const float* attnW    = (const float*)d_in[11];
    const float* attnB    = (const float*)d_in[12];
    const float* combW    = (const float*)d_in[13];
    const float* combB    = (const float*)d_in[14];
    const float* decWih   = (const float*)d_in[15];
    const float* decWhh   = (const float*)d_in[16];
    const float* decBih   = (const float*)d_in[17];
    const float* decBhh   = (const float*)d_in[18];
    const float* outW     = (const float*)d_in[19];
    const float* outB     = (const float*)d_in[20];
    float* out = (float*)d_out;

    cudaFuncSetAttribute(mmagemm_kernel, cudaFuncAttributeMaxDynamicSharedMemorySize, MG_SMEM);
    cudaFuncSetAttribute(mmagemm64_kernel, cudaFuncAttributeMaxDynamicSharedMemorySize, MG64_SMEM);
    cudaFuncSetAttribute(smctxcomb_kernel, cudaFuncAttributeMaxDynamicSharedMemorySize, FC_SMEM);

    float *catpre, *Mf, *gibias, *GIenc, *ENC, *M1, *c1, *c0fix, *Xe;
    float *Wstack, *bstack, *lp, *gbuf, *gigh, *ghb, *hb0, *hb1, *Hall;
    float *Wh_pad, *W2, *WexC, *bias384, *corr_l, *corr_c, *XLC;
    cudaGetSymbolAddress((void**)&catpre, g_catpre64);
    cudaGetSymbolAddress((void**)&Mf, g_Mf64);
    cudaGetSymbolAddress((void**)&gibias, g_gibias);
    cudaGetSymbolAddress((void**)&GIenc, g_GIenc);
    cudaGetSymbolAddress((void**)&ENC, g_ENC);
    cudaGetSymbolAddress((void**)&M1, g_M1);
    cudaGetSymbolAddress((void**)&c1, g_c1);
    cudaGetSymbolAddress((void**)&c0fix, g_c0fix);
    cudaGetSymbolAddress((void**)&Xe, g_Xe);
    cudaGetSymbolAddress((void**)&Wstack, g_Wstack);
    cudaGetSymbolAddress((void**)&bstack, g_bstack);
    cudaGetSymbolAddress((void**)&lp, g_lp);
    cudaGetSymbolAddress((void**)&gbuf, g_g);
    cudaGetSymbolAddress((void**)&gigh, g_gigh);
    cudaGetSymbolAddress((void**)&ghb, g_gh);
    cudaGetSymbolAddress((void**)&hb0, g_hbuf);
    hb1 = hb0 + B_ * H_;
    cudaGetSymbolAddress((void**)&Hall, g_Hall);
    cudaGetSymbolAddress((void**)&Wh_pad, g_Wh_pad);
    cudaGetSymbolAddress((void**)&W2, g_W2);
    cudaGetSymbolAddress((void**)&WexC, g_WexC);
    cudaGetSymbolAddress((void**)&bias384, g_bias384);
    cudaGetSymbolAddress((void**)&corr_l, g_corr_l);
    cudaGetSymbolAddress((void**)&corr_c, g_corr_c);
    cudaGetSymbolAddress((void**)&XLC, g_XLC);

    float* hb[2] = {hb0, hb1};

    // ---- prep ----
    pack_catpre_kernel<<<(LPRE * B_ * 64 + 255) / 256, 256>>>(pre_x, pre_y, catpre);
    make_Mf_kernel<<<(G3_ * 64 + G3_ + 255) / 256, 256>>>(encWih, encEmbW, encEmbB, encBih, Mf, gibias);
    make_M1_kernel<<<(H_ * H_ + H_ + 255) / 256, 256>>>(decEmbW, decEmbB, outW, outB, M1, c1, c0fix);
    stack_copy_kernel<<<(G3_ * H_ + 255) / 256, 256>>>(decWih, decWhh, decBih, decBhh, Wstack, bstack);
    zero_h_kernel<<<(B_ * H_ + 255) / 256, 256>>>(hb[0]);
    make_attnprep_kernel<<<(128 * H_ + 255) / 256, 256>>>(attnW, attnB, M1, c0fix,
                                                          WexC, Wh_pad, W2, bias384, corr_l);
    make_combprep_kernel<<<(H_ * H_ + 255) / 256, 256>>>(combW, combB, M1, c0fix,
                                                         WexC, W2, bias384, corr_c);

    // ---- prework GEMMs ----
    run_mma(catpre, 64, Mf, 64, gibias, GIenc, G3_, LPRE * B_, G3_, 64);
    {
        dim3 grid(H_ / 128, (LFWD * B_) / 128);
        mmagemm_kernel<<<grid, 256, MG_SMEM>>>(fwd_x, 32, decEmbW + 16, 48, c1, Xe, H_, LFWD * B_, H_, 32);
    }
    run_mma(Xe, 256, WexC, 256, bias384, XLC, 384, LFWD * B_, 384, 256);

    // ---- encoder: 60 steps ----
    int cur = 0;
    for (int t = 0; t < LPRE; t++) {
        run_mma64(hb[cur], hb[cur], 1 << 30, 256,
                  encWhh, H_, encBhh, nullptr, 0, ghb, G3_, B_, G3_, H_, 0);
        gates_kernel<<<B_, 256>>>(GIenc + (size_t)t * B_ * G3_, G3_, ghb, G3_,
                                  hb[cur], hb[cur ^ 1], ENC + (size_t)t * B_ * H_);
        cur ^= 1;
    }

    // ---- decoder: 80 steps, 4 kernels each ----
    for (int t = 0; t < LFWD; t++) {
        if (t == 0) {
            run_mma64(hb[cur], hb[cur], 1 << 30, 256,
                      Wh_pad, 256, corr_l, XLC, 384, lp, 384, B_, 128, 256, 0);
        } else {
            run_mma64(hb[cur], hb[cur], 1 << 30, 256,
                      W2, 256, nullptr, XLC + (size_t)t * B_ * 384, 384,
                      lp, 384, B_, 384, 256, 0);
        }
        smctxcomb_kernel<<<B_ / 16, 256, FC_SMEM>>>(
            lp, ENC, combW + 256,
            (t == 0) ? (XLC + 128) : (lp + 128),
            (t == 0) ? corr_c : nullptr,
            gbuf);
        run_mma64(gbuf, hb[cur], G3_, 256,
                  Wstack, H_, bstack, nullptr, 0, gigh, 2 * G3_, B_, 2 * G3_, H_, 0);
        gates_kernel<<<B_, 256>>>(gigh, 2 * G3_, gigh + G3_, 2 * G3_,
                                  hb[cur], hb[cur ^ 1], Hall + (size_t)t * B_ * H_);
        cur ^= 1;
    }

    // ---- final outputs: ys = Hall @ out_W.T + out_b ----
    {
        dim3 grid(1, (LFWD * B_) / 64);
        gemm_kernel<<<grid, 256>>>(Hall, outW, H_, outB, out, 16, LFWD * B_, 16, H_);
    }
}

// round 13
// speedup vs baseline: 1.0943x; 1.0943x over previous
#include <cuda_runtime.h>
#include <cuda_bf16.h>
#include <cstdint>
#include <math.h>

#define B_      1024
#define H_      256
#define G3_     768
#define LPRE    60
#define LFWD    80
#define ML_     80

// ---------------- static device scratch (no allocation) ----------------
__device__ float g_catpre64[LPRE * B_ * 64];
__device__ float g_Mf64[G3_ * 64];
__device__ float g_gibias[G3_];
__device__ float g_GIenc[LPRE * B_ * G3_];
__device__ float g_ENC[LPRE * B_ * H_];
__device__ float g_M1[H_ * H_];
__device__ float g_c1[H_];
__device__ float g_c0fix[H_];
__device__ float g_Xe[LFWD * B_ * H_];
__device__ float g_Wstack[2 * G3_ * H_];
__device__ float g_bstack[2 * G3_];
__device__ float g_ctx[B_ * H_];
__device__ float g_lp[B_ * 384];           // [logits(128) | pre(256)] per row
__device__ float g_g[B_ * H_];
__device__ float g_gigh[B_ * 2 * G3_];
__device__ float g_gh[B_ * G3_];
__device__ float g_hbuf[2][B_ * H_];
__device__ float g_Hall[LFWD * B_ * H_];
__device__ float g_Wh_pad[128 * H_];
__device__ float g_W2[384 * H_];           // rows 0-127: Wfuse, rows 128-383: Wch
__device__ float g_WexC[384 * H_];         // rows 0-127: We_pad, rows 128-383: combW_e
__device__ float g_bias384[384];           // [attn_b | comb_b]
__device__ float g_corr_l[128];
__device__ float g_corr_c[H_];             // combW_e . c0fix
__device__ float g_XLC[LFWD * B_ * 384];   // Xe@WexC^T + bias384

// ================= helpers =================
__device__ __forceinline__ uint32_t smem_u32(const void* p) {
    uint32_t a;
    asm("{ .reg .u64 t; cvta.to.shared.u64 t, %1; cvt.u32.u64 %0, t; }" : "=r"(a) : "l"(p));
    return a;
}

#define STS128(r0, r1, r2, r3, smem_addr) \
    asm volatile("st.shared.v4.b32 [%0], {%1, %2, %3, %4};" \
        :: "r"(smem_addr), "r"(r0), "r"(r1), "r"(r2), "r"(r3) : "memory")

#define LDSM4(r0, r1, r2, r3, addr) \
    asm volatile("ldmatrix.sync.aligned.m8n8.x4.shared.b16 {%0,%1,%2,%3}, [%4];" \
        : "=r"(r0), "=r"(r1), "=r"(r2), "=r"(r3) : "r"(addr))

#define MMA16816(d, a, b) \
    asm volatile("mma.sync.aligned.m16n8k16.row.col.f32.bf16.bf16.f32 " \
        "{%0,%1,%2,%3},{%4,%5,%6,%7},{%8,%9},{%0,%1,%2,%3};" \
        : "+f"((d)[0]), "+f"((d)[1]), "+f"((d)[2]), "+f"((d)[3]) \
        : "r"((a)[0]), "r"((a)[1]), "r"((a)[2]), "r"((a)[3]), "r"((b)[0]), "r"((b)[1]))

__device__ __forceinline__ void cvt_hl(float x, float y, uint32_t& h, uint32_t& l) {
    __nv_bfloat162 hb = __floats2bfloat162_rn(x, y);
    float rx = x - __low2float(hb);
    float ry = y - __high2float(hb);
    __nv_bfloat162 lb = __floats2bfloat162_rn(rx, ry);
    h = *reinterpret_cast<uint32_t*>(&hb);
    l = *reinterpret_cast<uint32_t*>(&lb);
}

__device__ __forceinline__ uint32_t swz(int r, int c) {
    return (uint32_t)(r * 64 + ((c ^ ((r >> 1) & 3)) << 4));
}

__device__ __forceinline__ void ldg16(const float* __restrict__ p, float* f) {
#pragma unroll
    for (int i = 0; i < 4; i++) {
        float4 v = *(const float4*)(p + 4 * i);
        f[4 * i + 0] = v.x; f[4 * i + 1] = v.y; f[4 * i + 2] = v.z; f[4 * i + 3] = v.w;
    }
}

__device__ __forceinline__ float sigm(float x) { return 1.f / (1.f + expf(-x)); }

__device__ __forceinline__ float gru1(float ir, float iz, float inn,
                                      float hr, float hz, float hn, float hp) {
    float r = sigm(ir + hr);
    float z = sigm(iz + hz);
    float n = tanhf(inn + r * hn);
    return (1.f - z) * n + z * hp;
}

__device__ __forceinline__ void sts_half(uint32_t sh, uint32_t sl, int row, int c0, const float* f) {
    uint32_t h[8], l[8];
#pragma unroll
    for (int i = 0; i < 8; i++) cvt_hl(f[2 * i], f[2 * i + 1], h[i], l[i]);
    uint32_t o0 = swz(row, c0), o1 = swz(row, c0 + 1);
    STS128(h[0], h[1], h[2], h[3], sh + o0);
    STS128(h[4], h[5], h[6], h[7], sh + o1);
    STS128(l[0], l[1], l[2], l[3], sl + o0);
    STS128(l[4], l[5], l[6], l[7], sl + o1);
}

// ================= BM=128 mma.sync bf16x3 GEMM (prework) =============
#define MG_SMEM (2 * 32768)
#define OFF_AH 0u
#define OFF_AL 8192u
#define OFF_BH 16384u
#define OFF_BL 24576u

__global__ __launch_bounds__(256, 1) void mmagemm_kernel(
    const float* __restrict__ A0, int lda0,
    const float* __restrict__ W, int ldw,
    const float* __restrict__ bias,
    float* __restrict__ C, int ldc,
    int M, int N, int K)
{
    extern __shared__ char dsm[];
    uint32_t sb = smem_u32(dsm);
    int tid = threadIdx.x, lane = tid & 31, wid = tid >> 5;
    int bm = blockIdx.y * 128, bn = blockIdx.x * 128;
    int warpM = wid & 3, warpN = wid >> 2;

    int lrow = tid >> 1, lhalf = tid & 1;
    const float* rowA = A0 + (size_t)(bm + lrow) * lda0 + lhalf * 16;
    const float* bp = W + (size_t)(bn + lrow) * ldw + lhalf * 16;

    float acc[2][8][4];
#pragma unroll
    for (int i = 0; i < 2; i++)
#pragma unroll
        for (int j = 0; j < 8; j++)
#pragma unroll
            for (int q = 0; q < 4; q++) acc[i][j][q] = 0.f;

    float fa[16], fb[16];
    int nk = K >> 5;

    ldg16(rowA, fa);
    ldg16(bp, fb);
    sts_half(sb + OFF_AH, sb + OFF_AL, lrow, lhalf * 2, fa);
    sts_half(sb + OFF_BH, sb + OFF_BL, lrow, lhalf * 2, fb);
    __syncthreads();

    for (int i = 0; i < nk; i++) {
        if (i + 1 < nk) {
            ldg16(rowA + (i + 1) * 32, fa);
            ldg16(bp + (i + 1) * 32, fb);
        }
        uint32_t st = sb + (uint32_t)(i & 1) * 32768u;
#pragma unroll
        for (int ks = 0; ks < 2; ks++) {
            uint32_t ah[2][4], al[2][4], bh[8][2], bl[8][2];
#pragma unroll
            for (int mf = 0; mf < 2; mf++) {
                int r = warpM * 32 + mf * 16 + (lane & 15);
                int c = ks * 2 + (lane >> 4);
                uint32_t o = swz(r, c);
                LDSM4(ah[mf][0], ah[mf][1], ah[mf][2], ah[mf][3], st + OFF_AH + o);
                LDSM4(al[mf][0], al[mf][1], al[mf][2], al[mf][3], st + OFF_AL + o);
            }
#pragma unroll
            for (int p = 0; p < 4; p++) {
                int r = warpN * 64 + p * 16 + (lane & 7) + ((lane >> 4) << 3);
                int c = ks * 2 + ((lane >> 3) & 1);
                uint32_t o = swz(r, c);
                LDSM4(bh[2 * p][0], bh[2 * p][1], bh[2 * p + 1][0], bh[2 * p + 1][1], st + OFF_BH + o);
                LDSM4(bl[2 * p][0], bl[2 * p][1], bl[2 * p + 1][0], bl[2 * p + 1][1], st + OFF_BL + o);
            }
#pragma unroll
            for (int mf = 0; mf < 2; mf++)
#pragma unroll
                for (int nf = 0; nf < 8; nf++) {
                    MMA16816(acc[mf][nf], ah[mf], bh[nf]);
                    MMA16816(acc[mf][nf], ah[mf], bl[nf]);
                    MMA16816(acc[mf][nf], al[mf], bh[nf]);
                }
        }
        if (i + 1 < nk) {
            uint32_t st2 = sb + (uint32_t)((i + 1) & 1) * 32768u;
            sts_half(st2 + OFF_AH, st2 + OFF_AL, lrow, lhalf * 2, fa);
            sts_half(st2 + OFF_BH, st2 + OFF_BL, lrow, lhalf * 2, fb);
            __syncthreads();
        }
    }

#pragma unroll
    for (int mf = 0; mf < 2; mf++)
#pragma unroll
        for (int nf = 0; nf < 8; nf++) {
            int m0 = bm + warpM * 32 + mf * 16 + (lane >> 2);
            int n = bn + warpN * 64 + nf * 8 + (lane & 3) * 2;
            float b0 = 0.f, b1 = 0.f;
            if (bias) { b0 = bias[n]; b1 = bias[n + 1]; }
#pragma unroll
            for (int hh = 0; hh < 2; hh++) {
                int m = m0 + hh * 8;
                float2 vv = make_float2(acc[mf][nf][2 * hh] + b0, acc[mf][nf][2 * hh + 1] + b1);
                *(float2*)(C + (size_t)m * ldc + n) = vv;
            }
        }
}

// ================= BM=64 mma GEMM (serial path) =================
#define MG64_SMEM (2 * 24576)
#define O64_AH 0u
#define O64_AL 4096u
#define O64_BH 8192u
#define O64_BL 16384u

__global__ __launch_bounds__(256, 1) void mmagemm64_kernel(
    const float* __restrict__ A0, const float* __restrict__ A1, int splitN, int lda0,
    const float* __restrict__ W, int ldw,
    const float* __restrict__ bias,
    const float* __restrict__ addmat, int ldadd,
    float* __restrict__ C, int ldc,
    int M, int N, int K, int act)
{
    extern __shared__ char dsm[];
    uint32_t sb = smem_u32(dsm);
    int tid = threadIdx.x, lane = tid & 31, wid = tid >> 5;
    int bm = blockIdx.y * 64, bn = blockIdx.x * 128;
    const float* __restrict__ A = (bn < splitN) ? A0 : A1;
    int warpM = wid & 1, warpN = wid >> 1;

    int lrow = tid >> 1, lhalf = tid & 1;
    int arow = (tid & 127) >> 1;
    bool doA = tid < 128;
    const float* rowA = A + (size_t)(bm + arow) * lda0 + lhalf * 16;
    const float* bp = W + (size_t)(bn + lrow) * ldw + lhalf * 16;

    float acc[2][4][4];
#pragma unroll
    for (int i = 0; i < 2; i++)
#pragma unroll
        for (int j = 0; j < 4; j++)
#pragma unroll
            for (int q = 0; q < 4; q++) acc[i][j][q] = 0.f;

    float fa[16], fb[16];
    int nk = K >> 5;

    {
        ldg16(bp, fb);
        if (doA) ldg16(rowA, fa);
        sts_half(sb + O64_BH, sb + O64_BL, lrow, lhalf * 2, fb);
        if (doA) sts_half(sb + O64_AH, sb + O64_AL, arow, lhalf * 2, fa);
    }
    __syncthreads();

    for (int i = 0; i < nk; i++) {
        if (i + 1 < nk) {
            int kk = (i + 1) * 32;
            ldg16(bp + kk, fb);
            if (doA) ldg16(rowA + kk, fa);
        }
        uint32_t st = sb + (uint32_t)(i & 1) * 24576u;
#pragma unroll
        for (int ks = 0; ks < 2; ks++) {
            uint32_t ah[2][4], al[2][4], bh[4][2], bl[4][2];
#pragma unroll
            for (int mf = 0; mf < 2; mf++) {
                int r = warpM * 32 + mf * 16 + (lane & 15);
                int c = ks * 2 + (lane >> 4);
                uint32_t o = swz(r, c);
                LDSM4(ah[mf][0], ah[mf][1], ah[mf][2], ah[mf][3], st + O64_AH + o);
                LDSM4(al[mf][0], al[mf][1], al[mf][2], al[mf][3], st + O64_AL + o);
            }
#pragma unroll
            for (int p = 0; p < 2; p++) {
                int r = warpN * 32 + p * 16 + (lane & 7) + ((lane >> 4) << 3);
                int c = ks * 2 + ((lane >> 3) & 1);
                uint32_t o = swz(r, c);
                LDSM4(bh[2 * p][0], bh[2 * p][1], bh[2 * p + 1][0], bh[2 * p + 1][1], st + O64_BH + o);
                LDSM4(bl[2 * p][0], bl[2 * p][1], bl[2 * p + 1][0], bl[2 * p + 1][1], st + O64_BL + o);
            }
#pragma unroll
            for (int mf = 0; mf < 2; mf++)
#pragma unroll
                for (int nf = 0; nf < 4; nf++) {
                    MMA16816(acc[mf][nf], ah[mf], bh[nf]);
                    MMA16816(acc[mf][nf], ah[mf], bl[nf]);
                    MMA16816(acc[mf][nf], al[mf], bh[nf]);
                }
        }
        if (i + 1 < nk) {
            uint32_t st2 = sb + (uint32_t)((i + 1) & 1) * 24576u;
            sts_half(st2 + O64_BH, st2 + O64_BL, lrow, lhalf * 2, fb);
            if (doA) sts_half(st2 + O64_AH, st2 + O64_AL, arow, lhalf * 2, fa);
            __syncthreads();
        }
    }

#pragma unroll
    for (int mf = 0; mf < 2; mf++)
#pragma unroll
        for (int nf = 0; nf < 4; nf++) {
            int m0 = bm + warpM * 32 + mf * 16 + (lane >> 2);
            int n = bn + warpN * 32 + nf * 8 + (lane & 3) * 2;
            float b0 = 0.f, b1 = 0.f;
            if (bias) { b0 = bias[n]; b1 = bias[n + 1]; }
#pragma unroll
            for (int hh = 0; hh < 2; hh++) {
                int m = m0 + hh * 8;
                float v0 = acc[mf][nf][2 * hh] + b0;
                float v1 = acc[mf][nf][2 * hh + 1] + b1;
                if (addmat) {
                    const float* am = addmat + (size_t)m * ldadd + n;
                    v0 += am[0]; v1 += am[1];
                }
                if (act == 1) { v0 = tanhf(v0); v1 = tanhf(v1); }
                float2 vv = make_float2(v0, v1);
                *(float2*)(C + (size_t)m * ldc + n) = vv;
            }
        }
}

// ---------------- SIMT fp32 GEMM (final output) ----------------
__global__ __launch_bounds__(256) void gemm_kernel(
    const float* __restrict__ A, const float* __restrict__ W, int ldw,
    const float* __restrict__ bias,
    float* __restrict__ C, int ldc,
    int M, int N, int K)
{
    __shared__ float As[16][64];
    __shared__ float Bs[16][64];
    int bn = blockIdx.x * 64;
    int bm = blockIdx.y * 64;

    int tid = threadIdx.x;
    int tx = tid & 15, ty = tid >> 4;
    int lr = tid >> 2;
    int lk = (tid & 3) * 4;

    float acc[4][4];
#pragma unroll
    for (int i = 0; i < 4; i++)
#pragma unroll
        for (int j = 0; j < 4; j++) acc[i][j] = 0.f;

    for (int k0 = 0; k0 < K; k0 += 16) {
        float4 a4 = *(const float4*)(A + (size_t)(bm + lr) * K + k0 + lk);
        As[lk + 0][lr] = a4.x; As[lk + 1][lr] = a4.y;
        As[lk + 2][lr] = a4.z; As[lk + 3][lr] = a4.w;
        float4 b4 = make_float4(0.f, 0.f, 0.f, 0.f);
        if (bn + lr < N)
            b4 = *(const float4*)(W + (size_t)(bn + lr) * ldw + k0 + lk);
        Bs[lk + 0][lr] = b4.x; Bs[lk + 1][lr] = b4.y;
        Bs[lk + 2][lr] = b4.z; Bs[lk + 3][lr] = b4.w;
        __syncthreads();
#pragma unroll
        for (int kk = 0; kk < 16; kk++) {
            float ra[4], rb[4];
#pragma unroll
            for (int i = 0; i < 4; i++) ra[i] = As[kk][ty * 4 + i];
#pragma unroll
            for (int j = 0; j < 4; j++) rb[j] = Bs[kk][tx * 4 + j];
#pragma unroll
            for (int i = 0; i < 4; i++)
#pragma unroll
                for (int j = 0; j < 4; j++) acc[i][j] += ra[i] * rb[j];
        }
        __syncthreads();
    }

#pragma unroll
    for (int i = 0; i < 4; i++) {
        int m = bm + ty * 4 + i;
#pragma unroll
        for (int j = 0; j < 4; j++) {
            int n = bn + tx * 4 + j;
            if (n < N)
                C[(size_t)m * ldc + n] = acc[i][j] + bias[n];
        }
    }
}

// ---------------- prep kernels ----------------
__global__ void pack_catpre_kernel(const float* __restrict__ px, const float* __restrict__ py,
                                   float* __restrict__ out)
{
    int idx = blockIdx.x * 256 + threadIdx.x;
    if (idx >= LPRE * B_ * 64) return;
    int c = idx & 63;
    int tb = idx >> 6;
    float v = 0.f;
    if (c < 32) v = px[(size_t)tb * 32 + c];
    else if (c < 48) v = py[(size_t)tb * 16 + (c - 32)];
    out[idx] = v;
}

__global__ void make_Mf_kernel(const float* __restrict__ Wih, const float* __restrict__ embW,
                               const float* __restrict__ embb, const float* __restrict__ bih,
                               float* __restrict__ Mf, float* __restrict__ gib)
{
    int idx = blockIdx.x * 256 + threadIdx.x;
    if (idx < G3_ * 64) {
        int i = idx >> 6, k = idx & 63;
        float s = 0.f;
        if (k < 48)
            for (int j = 0; j < H_; j++) s += Wih[(size_t)i * H_ + j] * embW[(size_t)j * 48 + k];
        Mf[idx] = s;
    } else if (idx < G3_ * 64 + G3_) {
        int i = idx - G3_ * 64;
        float s = bih[i];
        for (int j = 0; j < H_; j++) s += Wih[(size_t)i * H_ + j] * embb[j];
        gib[i] = s;
    }
}

__global__ void make_M1_kernel(const float* __restrict__ decEmbW, const float* __restrict__ decEmbb,
                               const float* __restrict__ outW, const float* __restrict__ outb,
                               float* __restrict__ M1, float* __restrict__ c1, float* __restrict__ c0fix)
{
    int idx = blockIdx.x * 256 + threadIdx.x;
    if (idx < H_ * H_) {
        int i = idx / H_, j = idx % H_;
        float s = 0.f;
        for (int k = 0; k < 16; k++) s += decEmbW[(size_t)i * 48 + k] * outW[(size_t)k * H_ + j];
        M1[idx] = s;
    } else if (idx < H_ * H_ + H_) {
        int i = idx - H_ * H_;
        float s = 0.f;
        for (int k = 0; k < 16; k++) s += decEmbW[(size_t)i * 48 + k] * outb[k];
        c1[i] = s + decEmbb[i];
        c0fix[i] = -s;
    }
}

__global__ void stack_copy_kernel(const float* __restrict__ Wih, const float* __restrict__ Whh,
                                  const float* __restrict__ bih, const float* __restrict__ bhh,
                                  float* __restrict__ Wst, float* __restrict__ bst)
{
    int idx = blockIdx.x * 256 + threadIdx.x;
    if (idx < G3_ * H_) {
        Wst[idx] = Wih[idx];
        Wst[G3_ * H_ + idx] = Whh[idx];
    }
    if (idx < G3_) { bst[idx] = bih[idx]; bst[G3_ + idx] = bhh[idx]; }
}

__global__ void zero_h_kernel(float* __restrict__ h)
{
    int idx = blockIdx.x * 256 + threadIdx.x;
    if (idx < B_ * H_) h[idx] = 0.f;
}

__global__ void make_attnprep_kernel(const float* __restrict__ attnW, const float* __restrict__ attnb,
                                     const float* __restrict__ M1, const float* __restrict__ c0fix,
                                     float* __restrict__ WexC, float* __restrict__ Wh_pad,
                                     float* __restrict__ W2, float* __restrict__ bias384,
                                     float* __restrict__ corr_l)
{
    int idx = blockIdx.x * 256 + threadIdx.x;
    if (idx >= 128 * H_) return;
    int m = idx >> 8, k = idx & 255;
    float we = 0.f, wh = 0.f, wf = 0.f;
    if (m < ML_) {
        we = attnW[(size_t)m * 512 + k];
        wh = attnW[(size_t)m * 512 + 256 + k];
        float s = wh;
        for (int j = 0; j < H_; j++) s += attnW[(size_t)m * 512 + j] * M1[(size_t)j * H_ + k];
        wf = s;
    }
    WexC[idx] = we; Wh_pad[idx] = wh; W2[idx] = wf;
    if (k == 0) {
        float ab = 0.f, cl = 0.f;
        if (m < ML_) {
            ab = attnb[m];
            for (int j = 0; j < H_; j++) cl += c0fix[j] * attnW[(size_t)m * 512 + j];
        }
        bias384[m] = ab;
        corr_l[m] = cl;
    }
}

__global__ void make_combprep_kernel(const float* __restrict__ combW, const float* __restrict__ combb,
                                     const float* __restrict__ M1, const float* __restrict__ c0fix,
                                     float* __restrict__ WexC, float* __restrict__ W2,
                                     float* __restrict__ bias384, float* __restrict__ corr_c)
{
    int idx = blockIdx.x * 256 + threadIdx.x;
    if (idx >= H_ * H_) return;
    int n = idx >> 8, k = idx & 255;
    float s = 0.f;
    for (int j = 0; j < H_; j++) s += combW[(size_t)n * 512 + j] * M1[(size_t)j * H_ + k];
    W2[(size_t)(128 + n) * H_ + k] = s;
    WexC[(size_t)(128 + n) * H_ + k] = combW[(size_t)n * 512 + k];
    if (k == 0) {
        bias384[128 + n] = combb[n];
        float cc = 0.f;
        for (int j = 0; j < H_; j++) cc += combW[(size_t)n * 512 + j] * c0fix[j];
        corr_c[n] = cc;
    }
}

// ---------------- GRU gates (float4-vectorized) ----------------
__global__ __launch_bounds__(256) void gates_kernel(
    const float* __restrict__ gi, int ldgi,
    const float* __restrict__ gh, int ldgh,
    const float* __restrict__ h,
    float* __restrict__ h2, float* __restrict__ out2)
{
    int idx = blockIdx.x * 256 + threadIdx.x;     // B_*64 threads total
    int b = idx >> 6, j = (idx & 63) << 2;
    const float* gib = gi + (size_t)b * ldgi + j;
    const float* ghp = gh + (size_t)b * ldgh + j;
    float4 ir  = *(const float4*)gib;
    float4 iz  = *(const float4*)(gib + 256);
    float4 inn = *(const float4*)(gib + 512);
    float4 hr  = *(const float4*)ghp;
    float4 hz  = *(const float4*)(ghp + 256);
    float4 hn  = *(const float4*)(ghp + 512);
    float4 hp  = *(const float4*)(h + (size_t)b * 256 + j);
    float4 v;
    v.x = gru1(ir.x, iz.x, inn.x, hr.x, hz.x, hn.x, hp.x);
    v.y = gru1(ir.y, iz.y, inn.y, hr.y, hz.y, hn.y, hp.y);
    v.z = gru1(ir.z, iz.z, inn.z, hr.z, hz.z, hn.z, hp.z);
    v.w = gru1(ir.w, iz.w, inn.w, hr.w, hz.w, hn.w, hp.w);
    *(float4*)(h2 + (size_t)b * 256 + j) = v;
    if (out2) *(float4*)(out2 + (size_t)b * 256 + j) = v;
}

// ---------------- softmax + context ----------------
__global__ __launch_bounds__(256) void smctx_kernel(
    const float* __restrict__ logits, int ldl,
    const float* __restrict__ ENC,
    float* __restrict__ ctx)
{
    int b = blockIdx.x;
    __shared__ float saw[ML_];
    int tid = threadIdx.x;

    if (tid < 32) {
        const float* lb = logits + (size_t)b * ldl;
        float x0 = lb[tid], x1 = lb[tid + 32];
        float x2 = (tid < 16) ? lb[tid + 64] : -1e30f;
        float mx = fmaxf(x0, fmaxf(x1, x2));
#pragma unroll
        for (int o = 16; o; o >>= 1) mx = fmaxf(mx, __shfl_xor_sync(0xffffffffu, mx, o));
        float e0 = expf(x0 - mx), e1 = expf(x1 - mx);
        float e2 = (tid < 16) ? expf(x2 - mx) : 0.f;
        float s = e0 + e1 + e2;
#pragma unroll
        for (int o = 16; o; o >>= 1) s += __shfl_xor_sync(0xffffffffu, s, o);
        float inv = 1.f / s;
        saw[tid] = e0 * inv;
        saw[tid + 32] = e1 * inv;
        if (tid < 16) saw[tid + 64] = e2 * inv;
    }
    __syncthreads();

    float acc = 0.f;
    const float* encb = ENC + (size_t)b * 256 + tid;
#pragma unroll 4
    for (int m = 0; m < LPRE; m++) acc += saw[m] * encb[(size_t)m * B_ * 256];
    ctx[(size_t)b * 256 + tid] = acc;
}

// ---------------- host launcher ----------------
static inline void run_mma_s(cudaStream_t st, const float* A, int lda, const float* W, int ldw,
                             const float* bias, float* C, int ldc, int M, int N, int K)
{
    dim3 grid(N / 128, M / 128);
    mmagemm_kernel<<<grid, 256, MG_SMEM, st>>>(A, lda, W, ldw, bias, C, ldc, M, N, K);
}

static inline void run_mma64(const float* A0, const float* A1, int splitN, int lda0,
                             const float* W, int ldw, const float* bias,
                             const float* addmat, int ldadd,
                             float* C, int ldc, int M, int N, int K, int act)
{
    dim3 grid(N / 128, M / 64);
    mmagemm64_kernel<<<grid, 256, MG64_SMEM>>>(A0, A1, splitN, lda0, W, ldw, bias,
                                               addmat, ldadd, C, ldc, M, N, K, act);
}

extern "C" void kernel_launch(void* const* d_in, const int* in_sizes, int n_in,
                              void* d_out, int out_size)
{
    const float* pre_x    = (const float*)d_in[0];
    const float* pre_y    = (const float*)d_in[1];
    const float* fwd_x    = (const float*)d_in[2];
    const float* encEmbW  = (const float*)d_in[3];
    const float* encEmbB  = (const float*)d_in[4];
    const float* encWih   = (const float*)d_in[5];
    const float* encWhh   = (const float*)d_in[6];
    const float* encBih   = (const float*)d_in[7];
    const float* encBhh   = (const float*)d_in[8];
    const float* decEmbW  = (const float*)d_in[9];
    const float* decEmbB  = (const float*)d_in[10];
    const float* attnW    = (const float*)d_in[11];
    const float* attnB    = (const float*)d_in[12];
    const float* combW    = (const float*)d_in[13];
    const float* combB    = (const float*)d_in[14];
    const float* decWih   = (const float*)d_in[15];
    const float* decWhh   = (const float*)d_in[16];
    const float* decBih   = (const float*)d_in[17];
    const float* decBhh   = (const float*)d_in[18];
    const float* outW     = (const float*)d_in[19];
    const float* outB     = (const float*)d_in[20];
    float* out = (float*)d_out;

    cudaFuncSetAttribute(mmagemm_kernel, cudaFuncAttributeMaxDynamicSharedMemorySize, MG_SMEM);
    cudaFuncSetAttribute(mmagemm64_kernel, cudaFuncAttributeMaxDynamicSharedMemorySize, MG64_SMEM);

    // one-time side stream + events (lazy create; no work depends on call count)
    static cudaStream_t s2 = nullptr;
    static cudaEvent_t evFork = nullptr, evGI = nullptr, evXLC = nullptr;
    if (!s2) {
        cudaStreamCreateWithFlags(&s2, cudaStreamNonBlocking);
        cudaEventCreateWithFlags(&evFork, cudaEventDisableTiming);
        cudaEventCreateWithFlags(&evGI, cudaEventDisableTiming);
        cudaEventCreateWithFlags(&evXLC, cudaEventDisableTiming);
    }

    float *catpre, *Mf, *gibias, *GIenc, *ENC, *M1, *c1, *c0fix, *Xe;
    float *Wstack, *bstack, *ctx, *lp, *gbuf, *gigh, *ghb, *hb0, *hb1, *Hall;
    float *Wh_pad, *W2, *WexC, *bias384, *corr_l, *corr_c, *XLC;
    cudaGetSymbolAddress((void**)&catpre, g_catpre64);
    cudaGetSymbolAddress((void**)&Mf, g_Mf64);
    cudaGetSymbolAddress((void**)&gibias, g_gibias);
    cudaGetSymbolAddress((void**)&GIenc, g_GIenc);
    cudaGetSymbolAddress((void**)&ENC, g_ENC);
    cudaGetSymbolAddress((void**)&M1, g_M1);
    cudaGetSymbolAddress((void**)&c1, g_c1);
    cudaGetSymbolAddress((void**)&c0fix, g_c0fix);
    cudaGetSymbolAddress((void**)&Xe, g_Xe);
    cudaGetSymbolAddress((void**)&Wstack, g_Wstack);
    cudaGetSymbolAddress((void**)&bstack, g_bstack);
    cudaGetSymbolAddress((void**)&ctx, g_ctx);
    cudaGetSymbolAddress((void**)&lp, g_lp);
    cudaGetSymbolAddress((void**)&gbuf, g_g);
    cudaGetSymbolAddress((void**)&gigh, g_gigh);
    cudaGetSymbolAddress((void**)&ghb, g_gh);
    cudaGetSymbolAddress((void**)&hb0, g_hbuf);
    hb1 = hb0 + B_ * H_;
    cudaGetSymbolAddress((void**)&Hall, g_Hall);
    cudaGetSymbolAddress((void**)&Wh_pad, g_Wh_pad);
    cudaGetSymbolAddress((void**)&W2, g_W2);
    cudaGetSymbolAddress((void**)&WexC, g_WexC);
    cudaGetSymbolAddress((void**)&bias384, g_bias384);
    cudaGetSymbolAddress((void**)&corr_l, g_corr_l);
    cudaGetSymbolAddress((void**)&corr_c, g_corr_c);
    cudaGetSymbolAddress((void**)&XLC, g_XLC);

    float* hb[2] = {hb0, hb1};

    // ---- prep (default stream) ----
    pack_catpre_kernel<<<(LPRE * B_ * 64 + 255) / 256, 256>>>(pre_x, pre_y, catpre);
    make_Mf_kernel<<<(G3_ * 64 + G3_ + 255) / 256, 256>>>(encWih, encEmbW, encEmbB, encBih, Mf, gibias);
    make_M1_kernel<<<(H_ * H_ + H_ + 255) / 256, 256>>>(decEmbW, decEmbB, outW, outB, M1, c1, c0fix);
    stack_copy_kernel<<<(G3_ * H_ + 255) / 256, 256>>>(decWih, decWhh, decBih, decBhh, Wstack, bstack);
    zero_h_kernel<<<(B_ * H_ + 255) / 256, 256>>>(hb[0]);
    make_attnprep_kernel<<<(128 * H_ + 255) / 256, 256>>>(attnW, attnB, M1, c0fix,
                                                          WexC, Wh_pad, W2, bias384, corr_l);
    make_combprep_kernel<<<(H_ * H_ + 255) / 256, 256>>>(combW, combB, M1, c0fix,
                                                         WexC, W2, bias384, corr_c);

    // ---- fork: prework GEMMs on side stream, overlapping the encoder ----
    cudaEventRecord(evFork, 0);
    cudaStreamWaitEvent(s2, evFork, 0);
    run_mma_s(s2, catpre, 64, Mf, 64, gibias, GIenc, G3_, LPRE * B_, G3_, 64);
    cudaEventRecord(evGI, s2);
    run_mma_s(s2, fwd_x, 32, decEmbW + 16, 48, c1, Xe, H_, LFWD * B_, H_, 32);
    run_mma_s(s2, Xe, 256, WexC, 256, bias384, XLC, 384, LFWD * B_, 384, 256);
    cudaEventRecord(evXLC, s2);

    // ---- encoder: 60 steps (default stream) ----
    int cur = 0;
    run_mma64(hb[cur], hb[cur], 1 << 30, 256,
              encWhh, H_, encBhh, nullptr, 0, ghb, G3_, B_, G3_, H_, 0);
    cudaStreamWaitEvent(0, evGI, 0);   // gates(0) needs GIenc
    gates_kernel<<<256, 256>>>(GIenc, G3_, ghb, G3_,
                               hb[cur], hb[cur ^ 1], ENC);
    cur ^= 1;
    for (int t = 1; t < LPRE; t++) {
        run_mma64(hb[cur], hb[cur], 1 << 30, 256,
                  encWhh, H_, encBhh, nullptr, 0, ghb, G3_, B_, G3_, H_, 0);
        gates_kernel<<<256, 256>>>(GIenc + (size_t)t * B_ * G3_, G3_, ghb, G3_,
                                   hb[cur], hb[cur ^ 1], ENC + (size_t)t * B_ * H_);
        cur ^= 1;
    }

    // ---- join: decoder needs XLC ----
    cudaStreamWaitEvent(0, evXLC, 0);

    // ---- decoder: 80 steps, 5 kernels each ----
    for (int t = 0; t < LFWD; t++) {
        if (t == 0) {
            run_mma64(hb[cur], hb[cur], 1 << 30, 256,
                      Wh_pad, 256, corr_l, XLC, 384, lp, 384, B_, 128, 256, 0);
        } else {
            run_mma64(hb[cur], hb[cur], 1 << 30, 256,
                      W2, 256, nullptr, XLC + (size_t)t * B_ * 384, 384,
                      lp, 384, B_, 384, 256, 0);
        }
        smctx_kernel<<<B_, 256>>>(lp, 384, ENC, ctx);
        if (t == 0) {
            run_mma64(ctx, ctx, 1 << 30, 256,
                      combW + 256, 512, corr_c, XLC + 128, 384, gbuf, H_, B_, H_, 256, 1);
        } else {
            run_mma64(ctx, ctx, 1 << 30, 256,
                      combW + 256, 512, nullptr, lp + 128, 384, gbuf, H_, B_, H_, 256, 1);
        }
        run_mma64(gbuf, hb[cur], G3_, 256,
                  Wstack, H_, bstack, nullptr, 0, gigh, 2 * G3_, B_, 2 * G3_, H_, 0);
        gates_kernel<<<256, 256>>>(gigh, 2 * G3_, gigh + G3_, 2 * G3_,
                                   hb[cur], hb[cur ^ 1], Hall + (size_t)t * B_ * H_);
        cur ^= 1;
    }

    // ---- final outputs: ys = Hall @ out_W.T + out_b ----
    {
        dim3 grid(1, (LFWD * B_) / 64);
        gemm_kernel<<<grid, 256>>>(Hall, outW, H_, outB, out, 16, LFWD * B_, 16, H_);
    }
}

// round 14
// speedup vs baseline: 1.1942x; 1.0913x over previous
#include <cuda_runtime.h>
#include <cuda_bf16.h>
#include <cstdint>
#include <math.h>

#define B_      1024
#define H_      256
#define G3_     768
#define LPRE    60
#define LFWD    80
#define ML_     80

// ---------------- static device scratch (no allocation) ----------------
__device__ float g_catpre64[LPRE * B_ * 64];
__device__ float g_Mf64[G3_ * 64];
__device__ float g_gibias[G3_];
__device__ float g_GIenc[LPRE * B_ * G3_];
__device__ float g_ENC[LPRE * B_ * H_];
__device__ float g_M1[H_ * H_];
__device__ float g_c1[H_];
__device__ float g_c0fix[H_];
__device__ float g_Xe[LFWD * B_ * H_];
__device__ float g_Wstack[2 * G3_ * H_];
__device__ float g_bstack[2 * G3_];
__device__ float g_ctx[B_ * H_];
__device__ float g_lp[B_ * 384];
__device__ float g_g[B_ * H_];
__device__ float g_gigh[B_ * 2 * G3_];
__device__ float g_gh[B_ * G3_];
__device__ float g_hbuf[2][B_ * H_];
__device__ float g_Hall[LFWD * B_ * H_];
__device__ float g_Wh_pad[128 * H_];
__device__ float g_W2[384 * H_];
__device__ float g_WexC[384 * H_];
__device__ float g_bias384[384];
__device__ float g_corr_l[128];
__device__ float g_corr_c[H_];
__device__ float g_XLC[LFWD * B_ * 384];
// packed pre-swizzled bf16 hi/lo weights (word count = N*K each)
__device__ uint32_t g_bWhh[768 * 256];
__device__ uint32_t g_bWstack[1536 * 256];
__device__ uint32_t g_bW2[384 * 256];
__device__ uint32_t g_bCombC[256 * 256];
__device__ uint32_t g_bWhPad[128 * 256];

// ================= helpers =================
__device__ __forceinline__ uint32_t smem_u32(const void* p) {
    uint32_t a;
    asm("{ .reg .u64 t; cvta.to.shared.u64 t, %1; cvt.u32.u64 %0, t; }" : "=r"(a) : "l"(p));
    return a;
}

#define STS128(r0, r1, r2, r3, smem_addr) \
    asm volatile("st.shared.v4.b32 [%0], {%1, %2, %3, %4};" \
        :: "r"(smem_addr), "r"(r0), "r"(r1), "r"(r2), "r"(r3) : "memory")

#define LDSM4(r0, r1, r2, r3, addr) \
    asm volatile("ldmatrix.sync.aligned.m8n8.x4.shared.b16 {%0,%1,%2,%3}, [%4];" \
        : "=r"(r0), "=r"(r1), "=r"(r2), "=r"(r3) : "r"(addr))

#define MMA16816(d, a, b) \
    asm volatile("mma.sync.aligned.m16n8k16.row.col.f32.bf16.bf16.f32 " \
        "{%0,%1,%2,%3},{%4,%5,%6,%7},{%8,%9},{%0,%1,%2,%3};" \
        : "+f"((d)[0]), "+f"((d)[1]), "+f"((d)[2]), "+f"((d)[3]) \
        : "r"((a)[0]), "r"((a)[1]), "r"((a)[2]), "r"((a)[3]), "r"((b)[0]), "r"((b)[1]))

__device__ __forceinline__ void cvt_hl(float x, float y, uint32_t& h, uint32_t& l) {
    __nv_bfloat162 hb = __floats2bfloat162_rn(x, y);
    float rx = x - __low2float(hb);
    float ry = y - __high2float(hb);
    __nv_bfloat162 lb = __floats2bfloat162_rn(rx, ry);
    h = *reinterpret_cast<uint32_t*>(&hb);
    l = *reinterpret_cast<uint32_t*>(&lb);
}

__device__ __forceinline__ uint32_t swz(int r, int c) {
    return (uint32_t)(r * 64 + ((c ^ ((r >> 1) & 3)) << 4));
}

__device__ __forceinline__ void ldg16(const float* __restrict__ p, float* f) {
#pragma unroll
    for (int i = 0; i < 4; i++) {
        float4 v = *(const float4*)(p + 4 * i);
        f[4 * i + 0] = v.x; f[4 * i + 1] = v.y; f[4 * i + 2] = v.z; f[4 * i + 3] = v.w;
    }
}

__device__ __forceinline__ float sigm(float x) { return 1.f / (1.f + expf(-x)); }

__device__ __forceinline__ float gru1(float ir, float iz, float inn,
                                      float hr, float hz, float hn, float hp) {
    float r = sigm(ir + hr);
    float z = sigm(iz + hz);
    float n = tanhf(inn + r * hn);
    return (1.f - z) * n + z * hp;
}

__device__ __forceinline__ void sts_half(uint32_t sh, uint32_t sl, int row, int c0, const float* f) {
    uint32_t h[8], l[8];
#pragma unroll
    for (int i = 0; i < 8; i++) cvt_hl(f[2 * i], f[2 * i + 1], h[i], l[i]);
    uint32_t o0 = swz(row, c0), o1 = swz(row, c0 + 1);
    STS128(h[0], h[1], h[2], h[3], sh + o0);
    STS128(h[4], h[5], h[6], h[7], sh + o1);
    STS128(l[0], l[1], l[2], l[3], sl + o0);
    STS128(l[4], l[5], l[6], l[7], sl + o1);
}

// ================= BM=128 mma.sync bf16x3 GEMM (prework) =============
#define MG_SMEM (2 * 32768)
#define OFF_AH 0u
#define OFF_AL 8192u
#define OFF_BH 16384u
#define OFF_BL 24576u

__global__ __launch_bounds__(256, 1) void mmagemm_kernel(
    const float* __restrict__ A0, int lda0,
    const float* __restrict__ W, int ldw,
    const float* __restrict__ bias,
    float* __restrict__ C, int ldc,
    int M, int N, int K)
{
    extern __shared__ char dsm[];
    uint32_t sb = smem_u32(dsm);
    int tid = threadIdx.x, lane = tid & 31, wid = tid >> 5;
    int bm = blockIdx.y * 128, bn = blockIdx.x * 128;
    int warpM = wid & 3, warpN = wid >> 2;

    int lrow = tid >> 1, lhalf = tid & 1;
    const float* rowA = A0 + (size_t)(bm + lrow) * lda0 + lhalf * 16;
    const float* bp = W + (size_t)(bn + lrow) * ldw + lhalf * 16;

    float acc[2][8][4];
#pragma unroll
    for (int i = 0; i < 2; i++)
#pragma unroll
        for (int j = 0; j < 8; j++)
#pragma unroll
            for (int q = 0; q < 4; q++) acc[i][j][q] = 0.f;

    float fa[16], fb[16];
    int nk = K >> 5;

    ldg16(rowA, fa);
    ldg16(bp, fb);
    sts_half(sb + OFF_AH, sb + OFF_AL, lrow, lhalf * 2, fa);
    sts_half(sb + OFF_BH, sb + OFF_BL, lrow, lhalf * 2, fb);
    __syncthreads();

    for (int i = 0; i < nk; i++) {
        if (i + 1 < nk) {
            ldg16(rowA + (i + 1) * 32, fa);
            ldg16(bp + (i + 1) * 32, fb);
        }
        uint32_t st = sb + (uint32_t)(i & 1) * 32768u;
#pragma unroll
        for (int ks = 0; ks < 2; ks++) {
            uint32_t ah[2][4], al[2][4], bh[8][2], bl[8][2];
#pragma unroll
            for (int mf = 0; mf < 2; mf++) {
                int r = warpM * 32 + mf * 16 + (lane & 15);
                int c = ks * 2 + (lane >> 4);
                uint32_t o = swz(r, c);
                LDSM4(ah[mf][0], ah[mf][1], ah[mf][2], ah[mf][3], st + OFF_AH + o);
                LDSM4(al[mf][0], al[mf][1], al[mf][2], al[mf][3], st + OFF_AL + o);
            }
#pragma unroll
            for (int p = 0; p < 4; p++) {
                int r = warpN * 64 + p * 16 + (lane & 7) + ((lane >> 4) << 3);
                int c = ks * 2 + ((lane >> 3) & 1);
                uint32_t o = swz(r, c);
                LDSM4(bh[2 * p][0], bh[2 * p][1], bh[2 * p + 1][0], bh[2 * p + 1][1], st + OFF_BH + o);
                LDSM4(bl[2 * p][0], bl[2 * p][1], bl[2 * p + 1][0], bl[2 * p + 1][1], st + OFF_BL + o);
            }
#pragma unroll
            for (int mf = 0; mf < 2; mf++)
#pragma unroll
                for (int nf = 0; nf < 8; nf++) {
                    MMA16816(acc[mf][nf], ah[mf], bh[nf]);
                    MMA16816(acc[mf][nf], ah[mf], bl[nf]);
                    MMA16816(acc[mf][nf], al[mf], bh[nf]);
                }
        }
        if (i + 1 < nk) {
            uint32_t st2 = sb + (uint32_t)((i + 1) & 1) * 32768u;
            sts_half(st2 + OFF_AH, st2 + OFF_AL, lrow, lhalf * 2, fa);
            sts_half(st2 + OFF_BH, st2 + OFF_BL, lrow, lhalf * 2, fb);
            __syncthreads();
        }
    }

#pragma unroll
    for (int mf = 0; mf < 2; mf++)
#pragma unroll
        for (int nf = 0; nf < 8; nf++) {
            int m0 = bm + warpM * 32 + mf * 16 + (lane >> 2);
            int n = bn + warpN * 64 + nf * 8 + (lane & 3) * 2;
            float b0 = 0.f, b1 = 0.f;
            if (bias) { b0 = bias[n]; b1 = bias[n + 1]; }
#pragma unroll
            for (int hh = 0; hh < 2; hh++) {
                int m = m0 + hh * 8;
                float2 vv = make_float2(acc[mf][nf][2 * hh] + b0, acc[mf][nf][2 * hh + 1] + b1);
                *(float2*)(C + (size_t)m * ldc + n) = vv;
            }
        }
}

// ================= BM=64 mma GEMM, packed pre-swizzled bf16 B =================
#define MG64_SMEM (2 * 24576)
#define O64_AH 0u
#define O64_AL 4096u
#define O64_BH 8192u
#define O64_BL 16384u

__global__ __launch_bounds__(256, 1) void mmagemm64b_kernel(
    const float* __restrict__ A0, const float* __restrict__ A1, int splitN, int lda0,
    const uint32_t* __restrict__ Bp,
    const float* __restrict__ bias,
    const float* __restrict__ addmat, int ldadd,
    float* __restrict__ C, int ldc,
    int M, int N, int K, int act)
{
    extern __shared__ char dsm[];
    uint32_t sb = smem_u32(dsm);
    int tid = threadIdx.x, lane = tid & 31, wid = tid >> 5;
    int bm = blockIdx.y * 64, bn = blockIdx.x * 128;
    const float* __restrict__ A = (bn < splitN) ? A0 : A1;
    int warpM = wid & 1, warpN = wid >> 1;

    int lrow = tid >> 1, lhalf = tid & 1;
    int arow = (tid & 127) >> 1;
    bool doA = tid < 128;
    const float* rowA = A + (size_t)(bm + arow) * lda0 + lhalf * 16;
    int nk = K >> 5;
    const uint32_t* bbase = Bp + (size_t)blockIdx.x * nk * 4096 + tid * 8;

    float acc[2][4][4];
#pragma unroll
    for (int i = 0; i < 2; i++)
#pragma unroll
        for (int j = 0; j < 4; j++)
#pragma unroll
            for (int q = 0; q < 4; q++) acc[i][j][q] = 0.f;

    float fa[16];
    uint4 hv0, hv1, lv0, lv1;
    uint32_t so0 = swz(lrow, lhalf * 2), so1 = swz(lrow, lhalf * 2 + 1);

    {
        const uint32_t* p = bbase;
        hv0 = *(const uint4*)p;            hv1 = *(const uint4*)(p + 4);
        lv0 = *(const uint4*)(p + 2048);   lv1 = *(const uint4*)(p + 2052);
        if (doA) ldg16(rowA, fa);
        STS128(hv0.x, hv0.y, hv0.z, hv0.w, sb + O64_BH + so0);
        STS128(hv1.x, hv1.y, hv1.z, hv1.w, sb + O64_BH + so1);
        STS128(lv0.x, lv0.y, lv0.z, lv0.w, sb + O64_BL + so0);
        STS128(lv1.x, lv1.y, lv1.z, lv1.w, sb + O64_BL + so1);
        if (doA) sts_half(sb + O64_AH, sb + O64_AL, arow, lhalf * 2, fa);
    }
    __syncthreads();

    for (int i = 0; i < nk; i++) {
        if (i + 1 < nk) {
            const uint32_t* p = bbase + (size_t)(i + 1) * 4096;
            hv0 = *(const uint4*)p;            hv1 = *(const uint4*)(p + 4);
            lv0 = *(const uint4*)(p + 2048);   lv1 = *(const uint4*)(p + 2052);
            if (doA) ldg16(rowA + (i + 1) * 32, fa);
        }
        uint32_t st = sb + (uint32_t)(i & 1) * 24576u;
#pragma unroll
        for (int ks = 0; ks < 2; ks++) {
            uint32_t ah[2][4], al[2][4], bh[4][2], bl[4][2];
#pragma unroll
            for (int mf = 0; mf < 2; mf++) {
                int r = warpM * 32 + mf * 16 + (lane & 15);
                int c = ks * 2 + (lane >> 4);
                uint32_t o = swz(r, c);
                LDSM4(ah[mf][0], ah[mf][1], ah[mf][2], ah[mf][3], st + O64_AH + o);
                LDSM4(al[mf][0], al[mf][1], al[mf][2], al[mf][3], st + O64_AL + o);
            }
#pragma unroll
            for (int p = 0; p < 2; p++) {
                int r = warpN * 32 + p * 16 + (lane & 7) + ((lane >> 4) << 3);
                int c = ks * 2 + ((lane >> 3) & 1);
                uint32_t o = swz(r, c);
                LDSM4(bh[2 * p][0], bh[2 * p][1], bh[2 * p + 1][0], bh[2 * p + 1][1], st + O64_BH + o);
                LDSM4(bl[2 * p][0], bl[2 * p][1], bl[2 * p + 1][0], bl[2 * p + 1][1], st + O64_BL + o);
            }
#pragma unroll
            for (int mf = 0; mf < 2; mf++)
#pragma unroll
                for (int nf = 0; nf < 4; nf++) {
                    MMA16816(acc[mf][nf], ah[mf], bh[nf]);
                    MMA16816(acc[mf][nf], ah[mf], bl[nf]);
                    MMA16816(acc[mf][nf], al[mf], bh[nf]);
                }
        }
        if (i + 1 < nk) {
            uint32_t st2 = sb + (uint32_t)((i + 1) & 1) * 24576u;
            STS128(hv0.x, hv0.y, hv0.z, hv0.w, st2 + O64_BH + so0);
            STS128(hv1.x, hv1.y, hv1.z, hv1.w, st2 + O64_BH + so1);
            STS128(lv0.x, lv0.y, lv0.z, lv0.w, st2 + O64_BL + so0);
            STS128(lv1.x, lv1.y, lv1.z, lv1.w, st2 + O64_BL + so1);
            if (doA) sts_half(st2 + O64_AH, st2 + O64_AL, arow, lhalf * 2, fa);
            __syncthreads();
        }
    }

#pragma unroll
    for (int mf = 0; mf < 2; mf++)
#pragma unroll
        for (int nf = 0; nf < 4; nf++) {
            int m0 = bm + warpM * 32 + mf * 16 + (lane >> 2);
            int n = bn + warpN * 32 + nf * 8 + (lane & 3) * 2;
            float b0 = 0.f, b1 = 0.f;
            if (bias) { b0 = bias[n]; b1 = bias[n + 1]; }
#pragma unroll
            for (int hh = 0; hh < 2; hh++) {
                int m = m0 + hh * 8;
                float v0 = acc[mf][nf][2 * hh] + b0;
                float v1 = acc[mf][nf][2 * hh + 1] + b1;
                if (addmat) {
                    const float* am = addmat + (size_t)m * ldadd + n;
                    v0 += am[0]; v1 += am[1];
                }
                if (act == 1) { v0 = tanhf(v0); v1 = tanhf(v1); }
                float2 vv = make_float2(v0, v1);
                *(float2*)(C + (size_t)m * ldc + n) = vv;
            }
        }
}

// ---------------- weight pre-conversion: fp32 -> packed swizzle-order bf16 hi/lo ------
__global__ void convB_kernel(const float* __restrict__ W, int ldw, int N, int K,
                             uint32_t* __restrict__ out)
{
    int L = blockIdx.x * 256 + threadIdx.x;
    int total = N * K / 2;
    if (L >= total) return;
    int nbi = L >> 11, rem = L & 2047;
    int t = rem >> 3, q = rem & 7;
    int which = q >> 2, w = q & 3;
    int kc = K >> 5;
    int nb = nbi / kc, i = nbi % kc;
    int lrow = t >> 1, lhalf = t & 1;
    int n = nb * 128 + lrow;
    int k = i * 32 + lhalf * 16 + 8 * which + 2 * w;
    float x = W[(size_t)n * ldw + k];
    float y = W[(size_t)n * ldw + k + 1];
    uint32_t h, l;
    cvt_hl(x, y, h, l);
    out[(size_t)nbi * 4096 + rem] = h;
    out[(size_t)nbi * 4096 + 2048 + rem] = l;
}

// ---------------- SIMT fp32 GEMM (final output) ----------------
__global__ __launch_bounds__(256) void gemm_kernel(
    const float* __restrict__ A, const float* __restrict__ W, int ldw,
    const float* __restrict__ bias,
    float* __restrict__ C, int ldc,
    int M, int N, int K)
{
    __shared__ float As[16][64];
    __shared__ float Bs[16][64];
    int bn = blockIdx.x * 64;
    int bm = blockIdx.y * 64;

    int tid = threadIdx.x;
    int tx = tid & 15, ty = tid >> 4;
    int lr = tid >> 2;
    int lk = (tid & 3) * 4;

    float acc[4][4];
#pragma unroll
    for (int i = 0; i < 4; i++)
#pragma unroll
        for (int j = 0; j < 4; j++) acc[i][j] = 0.f;

    for (int k0 = 0; k0 < K; k0 += 16) {
        float4 a4 = *(const float4*)(A + (size_t)(bm + lr) * K + k0 + lk);
        As[lk + 0][lr] = a4.x; As[lk + 1][lr] = a4.y;
        As[lk + 2][lr] = a4.z; As[lk + 3][lr] = a4.w;
        float4 b4 = make_float4(0.f, 0.f, 0.f, 0.f);
        if (bn + lr < N)
            b4 = *(const float4*)(W + (size_t)(bn + lr) * ldw + k0 + lk);
        Bs[lk + 0][lr] = b4.x; Bs[lk + 1][lr] = b4.y;
        Bs[lk + 2][lr] = b4.z; Bs[lk + 3][lr] = b4.w;
        __syncthreads();
#pragma unroll
        for (int kk = 0; kk < 16; kk++) {
            float ra[4], rb[4];
#pragma unroll
            for (int i = 0; i < 4; i++) ra[i] = As[kk][ty * 4 + i];
#pragma unroll
            for (int j = 0; j < 4; j++) rb[j] = Bs[kk][tx * 4 + j];
#pragma unroll
            for (int i = 0; i < 4; i++)
#pragma unroll
                for (int j = 0; j < 4; j++) acc[i][j] += ra[i] * rb[j];
        }
        __syncthreads();
    }

#pragma unroll
    for (int i = 0; i < 4; i++) {
        int m = bm + ty * 4 + i;
#pragma unroll
        for (int j = 0; j < 4; j++) {
            int n = bn + tx * 4 + j;
            if (n < N)
                C[(size_t)m * ldc + n] = acc[i][j] + bias[n];
        }
    }
}

// ---------------- prep kernels ----------------
__global__ void pack_catpre_kernel(const float* __restrict__ px, const float* __restrict__ py,
                                   float* __restrict__ out)
{
    int idx = blockIdx.x * 256 + threadIdx.x;
    if (idx >= LPRE * B_ * 64) return;
    int c = idx & 63;
    int tb = idx >> 6;
    float v = 0.f;
    if (c < 32) v = px[(size_t)tb * 32 + c];
    else if (c < 48) v = py[(size_t)tb * 16 + (c - 32)];
    out[idx] = v;
}

__global__ void make_Mf_kernel(const float* __restrict__ Wih, const float* __restrict__ embW,
                               const float* __restrict__ embb, const float* __restrict__ bih,
                               float* __restrict__ Mf, float* __restrict__ gib)
{
    int idx = blockIdx.x * 256 + threadIdx.x;
    if (idx < G3_ * 64) {
        int i = idx >> 6, k = idx & 63;
        float s = 0.f;
        if (k < 48)
            for (int j = 0; j < H_; j++) s += Wih[(size_t)i * H_ + j] * embW[(size_t)j * 48 + k];
        Mf[idx] = s;
    } else if (idx < G3_ * 64 + G3_) {
        int i = idx - G3_ * 64;
        float s = bih[i];
        for (int j = 0; j < H_; j++) s += Wih[(size_t)i * H_ + j] * embb[j];
        gib[i] = s;
    }
}

__global__ void make_M1_kernel(const float* __restrict__ decEmbW, const float* __restrict__ decEmbb,
                               const float* __restrict__ outW, const float* __restrict__ outb,
                               float* __restrict__ M1, float* __restrict__ c1, float* __restrict__ c0fix)
{
    int idx = blockIdx.x * 256 + threadIdx.x;
    if (idx < H_ * H_) {
        int i = idx / H_, j = idx % H_;
        float s = 0.f;
        for (int k = 0; k < 16; k++) s += decEmbW[(size_t)i * 48 + k] * outW[(size_t)k * H_ + j];
        M1[idx] = s;
    } else if (idx < H_ * H_ + H_) {
        int i = idx - H_ * H_;
        float s = 0.f;
        for (int k = 0; k < 16; k++) s += decEmbW[(size_t)i * 48 + k] * outb[k];
        c1[i] = s + decEmbb[i];
        c0fix[i] = -s;
    }
}

__global__ void stack_copy_kernel(const float* __restrict__ Wih, const float* __restrict__ Whh,
                                  const float* __restrict__ bih, const float* __restrict__ bhh,
                                  float* __restrict__ Wst, float* __restrict__ bst)
{
    int idx = blockIdx.x * 256 + threadIdx.x;
    if (idx < G3_ * H_) {
        Wst[idx] = Wih[idx];
        Wst[G3_ * H_ + idx] = Whh[idx];
    }
    if (idx < G3_) { bst[idx] = bih[idx]; bst[G3_ + idx] = bhh[idx]; }
}

__global__ void zero_h_kernel(float* __restrict__ h)
{
    int idx = blockIdx.x * 256 + threadIdx.x;
    if (idx < B_ * H_) h[idx] = 0.f;
}

__global__ void make_attnprep_kernel(const float* __restrict__ attnW, const float* __restrict__ attnb,
                                     const float* __restrict__ M1, const float* __restrict__ c0fix,
                                     float* __restrict__ WexC, float* __restrict__ Wh_pad,
                                     float* __restrict__ W2, float* __restrict__ bias384,
                                     float* __restrict__ corr_l)
{
    int idx = blockIdx.x * 256 + threadIdx.x;
    if (idx >= 128 * H_) return;
    int m = idx >> 8, k = idx & 255;
    float we = 0.f, wh = 0.f, wf = 0.f;
    if (m < ML_) {
        we = attnW[(size_t)m * 512 + k];
        wh = attnW[(size_t)m * 512 + 256 + k];
        float s = wh;
        for (int j = 0; j < H_; j++) s += attnW[(size_t)m * 512 + j] * M1[(size_t)j * H_ + k];
        wf = s;
    }
    WexC[idx] = we; Wh_pad[idx] = wh; W2[idx] = wf;
    if (k == 0) {
        float ab = 0.f, cl = 0.f;
        if (m < ML_) {
            ab = attnb[m];
            for (int j = 0; j < H_; j++) cl += c0fix[j] * attnW[(size_t)m * 512 + j];
        }
        bias384[m] = ab;
        corr_l[m] = cl;
    }
}

__global__ void make_combprep_kernel(const float* __restrict__ combW, const float* __restrict__ combb,
                                     const float* __restrict__ M1, const float* __restrict__ c0fix,
                                     float* __restrict__ WexC, float* __restrict__ W2,
                                     float* __restrict__ bias384, float* __restrict__ corr_c)
{
    int idx = blockIdx.x * 256 + threadIdx.x;
    if (idx >= H_ * H_) return;
    int n = idx >> 8, k = idx & 255;
    float s = 0.f;
    for (int j = 0; j < H_; j++) s += combW[(size_t)n * 512 + j] * M1[(size_t)j * H_ + k];
    W2[(size_t)(128 + n) * H_ + k] = s;
    WexC[(size_t)(128 + n) * H_ + k] = combW[(size_t)n * 512 + k];
    if (k == 0) {
        bias384[128 + n] = combb[n];
        float cc = 0.f;
        for (int j = 0; j < H_; j++) cc += combW[(size_t)n * 512 + j] * c0fix[j];
        corr_c[n] = cc;
    }
}

// ---------------- GRU gates (float4) ----------------
__global__ __launch_bounds__(256) void gates_kernel(
    const float* __restrict__ gi, int ldgi,
    const float* __restrict__ gh, int ldgh,
    const float* __restrict__ h,
    float* __restrict__ h2, float* __restrict__ out2)
{
    int idx = blockIdx.x * 256 + threadIdx.x;
    int b = idx >> 6, j = (idx & 63) << 2;
    const float* gib = gi + (size_t)b * ldgi + j;
    const float* ghp = gh + (size_t)b * ldgh + j;
    float4 ir  = *(const float4*)gib;
    float4 iz  = *(const float4*)(gib + 256);
    float4 inn = *(const float4*)(gib + 512);
    float4 hr  = *(const float4*)ghp;
    float4 hz  = *(const float4*)(ghp + 256);
    float4 hn  = *(const float4*)(ghp + 512);
    float4 hp  = *(const float4*)(h + (size_t)b * 256 + j);
    float4 v;
    v.x = gru1(ir.x, iz.x, inn.x, hr.x, hz.x, hn.x, hp.x);
    v.y = gru1(ir.y, iz.y, inn.y, hr.y, hz.y, hn.y, hp.y);
    v.z = gru1(ir.z, iz.z, inn.z, hr.z, hz.z, hn.z, hp.z);
    v.w = gru1(ir.w, iz.w, inn.w, hr.w, hz.w, hn.w, hp.w);
    *(float4*)(h2 + (size_t)b * 256 + j) = v;
    if (out2) *(float4*)(out2 + (size_t)b * 256 + j) = v;
}

// ---------------- softmax + context ----------------
__global__ __launch_bounds__(256) void smctx_kernel(
    const float* __restrict__ logits, int ldl,
    const float* __restrict__ ENC,
    float* __restrict__ ctx)
{
    int b = blockIdx.x;
    __shared__ float saw[ML_];
    int tid = threadIdx.x;

    if (tid < 32) {
        const float* lb = logits + (size_t)b * ldl;
        float x0 = lb[tid], x1 = lb[tid + 32];
        float x2 = (tid < 16) ? lb[tid + 64] : -1e30f;
        float mx = fmaxf(x0, fmaxf(x1, x2));
#pragma unroll
        for (int o = 16; o; o >>= 1) mx = fmaxf(mx, __shfl_xor_sync(0xffffffffu, mx, o));
        float e0 = expf(x0 - mx), e1 = expf(x1 - mx);
        float e2 = (tid < 16) ? expf(x2 - mx) : 0.f;
        float s = e0 + e1 + e2;
#pragma unroll
        for (int o = 16; o; o >>= 1) s += __shfl_xor_sync(0xffffffffu, s, o);
        float inv = 1.f / s;
        saw[tid] = e0 * inv;
        saw[tid + 32] = e1 * inv;
        if (tid < 16) saw[tid + 64] = e2 * inv;
    }
    __syncthreads();

    float acc = 0.f;
    const float* encb = ENC + (size_t)b * 256 + tid;
#pragma unroll 4
    for (int m = 0; m < LPRE; m++) acc += saw[m] * encb[(size_t)m * B_ * 256];
    ctx[(size_t)b * 256 + tid] = acc;
}

// ---------------- host launcher ----------------
static inline void run_mma(const float* A, int lda, const float* W, int ldw,
                           const float* bias, float* C, int ldc, int M, int N, int K)
{
    dim3 grid(N / 128, M / 128);
    mmagemm_kernel<<<grid, 256, MG_SMEM>>>(A, lda, W, ldw, bias, C, ldc, M, N, K);
}

static inline void run_mma64b(const float* A0, const float* A1, int splitN, int lda0,
                              const uint32_t* Bp, const float* bias,
                              const float* addmat, int ldadd,
                              float* C, int ldc, int M, int N, int K, int act)
{
    dim3 grid(N / 128, M / 64);
    mmagemm64b_kernel<<<grid, 256, MG64_SMEM>>>(A0, A1, splitN, lda0, Bp, bias,
                                                addmat, ldadd, C, ldc, M, N, K, act);
}

static inline void run_convB(const float* W, int ldw, int N, int K, uint32_t* out)
{
    convB_kernel<<<(N * K / 2 + 255) / 256, 256>>>(W, ldw, N, K, out);
}

extern "C" void kernel_launch(void* const* d_in, const int* in_sizes, int n_in,
                              void* d_out, int out_size)
{
    const float* pre_x    = (const float*)d_in[0];
    const float* pre_y    = (const float*)d_in[1];
    const float* fwd_x    = (const float*)d_in[2];
    const float* encEmbW  = (const float*)d_in[3];
    const float* encEmbB  = (const float*)d_in[4];
    const float* encWih   = (const float*)d_in[5];
    const float* encWhh   = (const float*)d_in[6];
    const float* encBih   = (const float*)d_in[7];
    const float* encBhh   = (const float*)d_in[8];
    const float* decEmbW  = (const float*)d_in[9];
    const float* decEmbB  = (const float*)d_in[10];
    const float* attnW    = (const float*)d_in[11];
    const float* attnB    = (const float*)d_in[12];
    const float* combW    = (const float*)d_in[13];
    const float* combB    = (const float*)d_in[14];
    const float* decWih   = (const float*)d_in[15];
    const float* decWhh   = (const float*)d_in[16];
    const float* decBih   = (const float*)d_in[17];
    const float* decBhh   = (const float*)d_in[18];
    const float* outW     = (const float*)d_in[19];
    const float* outB     = (const float*)d_in[20];
    float* out = (float*)d_out;

    cudaFuncSetAttribute(mmagemm_kernel, cudaFuncAttributeMaxDynamicSharedMemorySize, MG_SMEM);
    cudaFuncSetAttribute(mmagemm64b_kernel, cudaFuncAttributeMaxDynamicSharedMemorySize, MG64_SMEM);

    float *catpre, *Mf, *gibias, *GIenc, *ENC, *M1, *c1, *c0fix, *Xe;
    float *Wstack, *bstack, *ctx, *lp, *gbuf, *gigh, *ghb, *hb0, *hb1, *Hall;
    float *Wh_pad, *W2, *WexC, *bias384, *corr_l, *corr_c, *XLC;
    uint32_t *bWhh, *bWstack, *bW2, *bCombC, *bWhPad;
    cudaGetSymbolAddress((void**)&catpre, g_catpre64);
    cudaGetSymbolAddress((void**)&Mf, g_Mf64);
    cudaGetSymbolAddress((void**)&gibias, g_gibias);
    cudaGetSymbolAddress((void**)&GIenc, g_GIenc);
    cudaGetSymbolAddress((void**)&ENC, g_ENC);
    cudaGetSymbolAddress((void**)&M1, g_M1);
    cudaGetSymbolAddress((void**)&c1, g_c1);
    cudaGetSymbolAddress((void**)&c0fix, g_c0fix);
    cudaGetSymbolAddress((void**)&Xe, g_Xe);
    cudaGetSymbolAddress((void**)&Wstack, g_Wstack);
    cudaGetSymbolAddress((void**)&bstack, g_bstack);
    cudaGetSymbolAddress((void**)&ctx, g_ctx);
    cudaGetSymbolAddress((void**)&lp, g_lp);
    cudaGetSymbolAddress((void**)&gbuf, g_g);
    cudaGetSymbolAddress((void**)&gigh, g_gigh);
    cudaGetSymbolAddress((void**)&ghb, g_gh);
    cudaGetSymbolAddress((void**)&hb0, g_hbuf);
    hb1 = hb0 + B_ * H_;
    cudaGetSymbolAddress((void**)&Hall, g_Hall);
    cudaGetSymbolAddress((void**)&Wh_pad, g_Wh_pad);
    cudaGetSymbolAddress((void**)&W2, g_W2);
    cudaGetSymbolAddress((void**)&WexC, g_WexC);
    cudaGetSymbolAddress((void**)&bias384, g_bias384);
    cudaGetSymbolAddress((void**)&corr_l, g_corr_l);
    cudaGetSymbolAddress((void**)&corr_c, g_corr_c);
    cudaGetSymbolAddress((void**)&XLC, g_XLC);
    cudaGetSymbolAddress((void**)&bWhh, g_bWhh);
    cudaGetSymbolAddress((void**)&bWstack, g_bWstack);
    cudaGetSymbolAddress((void**)&bW2, g_bW2);
    cudaGetSymbolAddress((void**)&bCombC, g_bCombC);
    cudaGetSymbolAddress((void**)&bWhPad, g_bWhPad);

    float* hb[2] = {hb0, hb1};

    // ---- prep ----
    pack_catpre_kernel<<<(LPRE * B_ * 64 + 255) / 256, 256>>>(pre_x, pre_y, catpre);
    make_Mf_kernel<<<(G3_ * 64 + G3_ + 255) / 256, 256>>>(encWih, encEmbW, encEmbB, encBih, Mf, gibias);
    make_M1_kernel<<<(H_ * H_ + H_ + 255) / 256, 256>>>(decEmbW, decEmbB, outW, outB, M1, c1, c0fix);
    stack_copy_kernel<<<(G3_ * H_ + 255) / 256, 256>>>(decWih, decWhh, decBih, decBhh, Wstack, bstack);
    zero_h_kernel<<<(B_ * H_ + 255) / 256, 256>>>(hb[0]);
    make_attnprep_kernel<<<(128 * H_ + 255) / 256, 256>>>(attnW, attnB, M1, c0fix,
                                                          WexC, Wh_pad, W2, bias384, corr_l);
    make_combprep_kernel<<<(H_ * H_ + 255) / 256, 256>>>(combW, combB, M1, c0fix,
                                                         WexC, W2, bias384, corr_c);

    // ---- weight pre-conversion ----
    run_convB(encWhh, 256, G3_, 256, bWhh);
    run_convB(Wstack, 256, 2 * G3_, 256, bWstack);
    run_convB(W2, 256, 384, 256, bW2);
    run_convB(combW + 256, 512, 256, 256, bCombC);
    run_convB(Wh_pad, 256, 128, 256, bWhPad);

    // ---- prework GEMMs ----
    run_mma(catpre, 64, Mf, 64, gibias, GIenc, G3_, LPRE * B_, G3_, 64);
    {
        dim3 grid(H_ / 128, (LFWD * B_) / 128);
        mmagemm_kernel<<<grid, 256, MG_SMEM>>>(fwd_x, 32, decEmbW + 16, 48, c1, Xe, H_, LFWD * B_, H_, 32);
    }
    run_mma(Xe, 256, WexC, 256, bias384, XLC, 384, LFWD * B_, 384, 256);

    // ---- encoder: 60 steps ----
    int cur = 0;
    for (int t = 0; t < LPRE; t++) {
        run_mma64b(hb[cur], hb[cur], 1 << 30, 256,
                   bWhh, encBhh, nullptr, 0, ghb, G3_, B_, G3_, H_, 0);
        gates_kernel<<<256, 256>>>(GIenc + (size_t)t * B_ * G3_, G3_, ghb, G3_,
                                   hb[cur], hb[cur ^ 1], ENC + (size_t)t * B_ * H_);
        cur ^= 1;
    }

    // ---- decoder: 80 steps ----
    for (int t = 0; t < LFWD; t++) {
        if (t == 0) {
            run_mma64b(hb[cur], hb[cur], 1 << 30, 256,
                       bWhPad, corr_l, XLC, 384, lp, 384, B_, 128, 256, 0);
        } else {
            run_mma64b(hb[cur], hb[cur], 1 << 30, 256,
                       bW2, nullptr, XLC + (size_t)t * B_ * 384, 384,
                       lp, 384, B_, 384, 256, 0);
        }
        smctx_kernel<<<B_, 256>>>(lp, 384, ENC, ctx);
        if (t == 0) {
            run_mma64b(ctx, ctx, 1 << 30, 256,
                       bCombC, corr_c, XLC + 128, 384, gbuf, H_, B_, H_, 256, 1);
        } else {
            run_mma64b(ctx, ctx, 1 << 30, 256,
                       bCombC, nullptr, lp + 128, 384, gbuf, H_, B_, H_, 256, 1);
        }
        run_mma64b(gbuf, hb[cur], G3_, 256,
                   bWstack, bstack, nullptr, 0, gigh, 2 * G3_, B_, 2 * G3_, H_, 0);
        gates_kernel<<<256, 256>>>(gigh, 2 * G3_, gigh + G3_, 2 * G3_,
                                   hb[cur], hb[cur ^ 1], Hall + (size_t)t * B_ * H_);
        cur ^= 1;
    }

    // ---- final outputs: ys = Hall @ out_W.T + out_b ----
    {
        dim3 grid(1, (LFWD * B_) / 64);
        gemm_kernel<<<grid, 256>>>(Hall, outW, H_, outB, out, 16, LFWD * B_, 16, H_);
    }
}